// round 2
// baseline (speedup 1.0000x reference)
#include <cuda_runtime.h>
#include <math.h>

#define NN 100000
#define NE 3200000
#define HID 32
#define NG 1000
#define NPG 100
#define KTOP 35

// ---------------- scratch (static device globals; no allocation) ------------
__device__ float g_deg[NN];
__device__ float g_dis[NN];     // rsqrt(deg)
__device__ float g_inv[NN];     // 1/deg
__device__ float g_h[NN * HID];   // h = in @ W
__device__ float g_agg[NN * HID]; // aggregation buffer
__device__ float g_in[NN * HID];  // layer input (tanh output of prev layer)
__device__ float g_feat[NN * 128]; // concat of 4 layer outputs

// ---------------- degree ----------------------------------------------------
__global__ void deg_init() {
    int i = blockIdx.x * 256 + threadIdx.x;
    if (i < NN) g_deg[i] = 1.0f;   // self loop
}
__global__ void deg_count(const int* __restrict__ ei) {
    int e = blockIdx.x * 256 + threadIdx.x;
    if (e < NE) {
        int d = ei[NE + e];
        atomicAdd(&g_deg[d], 1.0f);
    }
}
__global__ void deg_finish() {
    int i = blockIdx.x * 256 + threadIdx.x;
    if (i < NN) {
        float dg = g_deg[i];
        g_dis[i] = rsqrtf(dg);
        g_inv[i] = 1.0f / dg;
    }
}

// ------- per-layer GEMM: g_h = in @ W; also g_agg = g_h * inv (self loop) ---
__global__ void gemm_kernel(const float* __restrict__ x,
                            const float* __restrict__ w,
                            int IF, int use_x) {
    __shared__ float s_in[8 * 128];
    __shared__ float s_w[128 * 32];
    const float* in = use_x ? x : g_in;
    int tid = threadIdx.x;
    int node0 = blockIdx.x * 8;
    for (int i = tid; i < IF * 32; i += 256) s_w[i] = w[i];
    for (int i = tid; i < 8 * IF; i += 256) {
        int nl = i / IF, k = i - nl * IF;
        int node = node0 + nl;
        s_in[nl * IF + k] = (node < NN) ? in[node * IF + k] : 0.0f;
    }
    __syncthreads();
    int nl = tid >> 5, col = tid & 31;
    int node = node0 + nl;
    if (node >= NN) return;
    float acc = 0.0f;
    const float* si = &s_in[nl * IF];
#pragma unroll 4
    for (int k = 0; k < IF; ++k) acc += si[k] * s_w[k * 32 + col];
    g_h[node * 32 + col] = acc;
    g_agg[node * 32 + col] = acc * g_inv[node];  // self-loop contribution
}

// ---------------- edge scatter: warp per edge, lane = channel ---------------
__global__ void scatter(const int* __restrict__ ei) {
    long long gt = (long long)blockIdx.x * 256 + threadIdx.x;
    int e = (int)(gt >> 5);
    if (e >= NE) return;
    int lane = threadIdx.x & 31;
    int s = ei[e];
    int d = ei[NE + e];
    float coef = g_dis[s] * g_dis[d];
    atomicAdd(&g_agg[d * 32 + lane], g_h[s * 32 + lane] * coef);
}

// ---------------- tanh + bias; write next input + feat ----------------------
__global__ void finish(const float* __restrict__ b, int layer) {
    int i = blockIdx.x * 256 + threadIdx.x;
    if (i >= NN * HID) return;
    int col = i & 31;
    int node = i >> 5;
    float v = tanhf(g_agg[i] + b[col]);
    g_in[i] = v;
    g_feat[node * 128 + layer * 32 + col] = v;
}

// ---------------- head: sort-pool + conv1 + maxpool + conv2 + fc1 + fc2 -----
__global__ void head_kernel(const float* __restrict__ c1w, const float* __restrict__ c1b,
                            const float* __restrict__ c2w, const float* __restrict__ c2b,
                            const float* __restrict__ f1w, const float* __restrict__ f1b,
                            const float* __restrict__ f2w, const float* __restrict__ f2b,
                            float* __restrict__ out) {
    __shared__ float s_last[NPG];
    __shared__ int   s_ord[KTOP];
    __shared__ float s_top[KTOP * 128];   // 17.5 KB
    __shared__ float s_y[16 * KTOP];      // conv1 out [16,35]
    __shared__ float s_p[16 * 17];        // maxpool out
    __shared__ float s_z[32 * 13];        // conv2 out (flattened 416)
    __shared__ float s_f[128];            // fc1 out
    __shared__ float s_red[128];

    int g = blockIdx.x;
    int tid = threadIdx.x;
    int base = g * NPG;

    // 1) load last channel
    if (tid < NPG) s_last[tid] = g_feat[(base + tid) * 128 + 127];
    __syncthreads();

    // 2) stable rank (descending; ties -> lower index first), matches argsort(-x)
    if (tid < NPG) {
        float v = s_last[tid];
        int rank = 0;
#pragma unroll 4
        for (int j = 0; j < NPG; ++j) {
            float vj = s_last[j];
            rank += (vj > v) || (vj == v && j < tid);
        }
        if (rank < KTOP) s_ord[rank] = tid;
    }
    __syncthreads();

    // 3) gather top-K feature rows
    for (int t = tid; t < KTOP * 128; t += 128) {
        int k = t >> 7, c = t & 127;
        s_top[t] = g_feat[(base + s_ord[k]) * 128 + c];
    }
    __syncthreads();

    // 4) conv1 (1x1 over channels) + relu : y[o,k] = relu(sum_c w[o,c]*top[k,c]+b)
    for (int t = tid; t < 16 * KTOP; t += 128) {
        int o = t / KTOP, k = t - o * KTOP;
        float acc = c1b[o];
        const float* wr = &c1w[o * 128];
        const float* tr = &s_top[k * 128];
#pragma unroll 8
        for (int c = 0; c < 128; ++c) acc += wr[c] * tr[c];
        s_y[o * KTOP + k] = fmaxf(acc, 0.0f);
    }
    __syncthreads();

    // 5) maxpool1d(2): 35 -> 17
    for (int t = tid; t < 16 * 17; t += 128) {
        int o = t / 17, l = t - o * 17;
        s_p[t] = fmaxf(s_y[o * KTOP + 2 * l], s_y[o * KTOP + 2 * l + 1]);
    }
    __syncthreads();

    // 6) conv2 (k=5, valid): z[oc,t] over 16 in-ch; 17 -> 13
    for (int t = tid; t < 32 * 13; t += 128) {
        int oc = t / 13, tt = t - oc * 13;
        float acc = c2b[oc];
        const float* wr = &c2w[oc * 80];
#pragma unroll
        for (int ic = 0; ic < 16; ++ic) {
            const float* pr = &s_p[ic * 17 + tt];
#pragma unroll
            for (int j = 0; j < 5; ++j) acc += wr[ic * 5 + j] * pr[j];
        }
        s_z[t] = fmaxf(acc, 0.0f);
    }
    __syncthreads();

    // 7) fc1: 416 -> 128, relu
    {
        float acc = f1b[tid];
        const float* wr = &f1w[tid * 416];
#pragma unroll 8
        for (int v = 0; v < 416; ++v) acc += wr[v] * s_z[v];
        s_f[tid] = fmaxf(acc, 0.0f);
    }
    __syncthreads();

    // 8) fc2: 128 -> 1, sigmoid
    s_red[tid] = f2w[tid] * s_f[tid];
    __syncthreads();
    for (int off = 64; off > 0; off >>= 1) {
        if (tid < off) s_red[tid] += s_red[tid + off];
        __syncthreads();
    }
    if (tid == 0) {
        float z = s_red[0] + f2b[0];
        out[g] = 1.0f / (1.0f + expf(-z));
    }
}

// ---------------- launch -----------------------------------------------------
extern "C" void kernel_launch(void* const* d_in, const int* in_sizes, int n_in,
                              void* d_out, int out_size) {
    const float* x  = (const float*)d_in[0];
    const int*   ei = (const int*)d_in[1];   // int32! (JAX x64 disabled)
    // d_in[2] = batch (unused; graphs are contiguous blocks of 100)
    const float* w[4] = {(const float*)d_in[3], (const float*)d_in[5],
                         (const float*)d_in[7], (const float*)d_in[9]};
    const float* b[4] = {(const float*)d_in[4], (const float*)d_in[6],
                         (const float*)d_in[8], (const float*)d_in[10]};
    const float* c1w = (const float*)d_in[11];
    const float* c1b = (const float*)d_in[12];
    const float* c2w = (const float*)d_in[13];
    const float* c2b = (const float*)d_in[14];
    const float* f1w = (const float*)d_in[15];
    const float* f1b = (const float*)d_in[16];
    const float* f2w = (const float*)d_in[17];
    const float* f2b = (const float*)d_in[18];
    float* out = (float*)d_out;

    deg_init  <<<(NN + 255) / 256, 256>>>();
    deg_count <<<(NE + 255) / 256, 256>>>(ei);
    deg_finish<<<(NN + 255) / 256, 256>>>();

    const int gemm_blocks = (NN + 7) / 8;
    const int nh_blocks   = (NN * HID + 255) / 256;
    const long long sc_threads = (long long)NE * 32;
    const int sc_blocks = (int)((sc_threads + 255) / 256);

    for (int layer = 0; layer < 4; ++layer) {
        int IF = (layer == 0) ? 128 : 32;
        gemm_kernel<<<gemm_blocks, 256>>>(x, w[layer], IF, layer == 0 ? 1 : 0);
        scatter    <<<sc_blocks, 256>>>(ei);
        finish     <<<nh_blocks, 256>>>(b[layer], layer);
    }

    head_kernel<<<NG, 128>>>(c1w, c1b, c2w, c2b, f1w, f1b, f2w, f2b, out);
}

// round 4
// speedup vs baseline: 2.0963x; 2.0963x over previous
#include <cuda_runtime.h>
#include <math.h>

#define NN 100000
#define NE 3200000
#define HID 32
#define NG 1000
#define NPG 100
#define KTOP 35
#define SCAN_B 1024
#define SCAN_NB ((NN + SCAN_B - 1) / SCAN_B)   // 98

// ---------------- scratch (static device globals; no allocation) ------------
__device__ int   g_cnt[NN];        // in-degree (excl self)
__device__ int   g_fill[NN];       // fill cursor
__device__ int   g_rowptr[NN + 1]; // CSR row pointers
__device__ int   g_csr[NE];        // CSR src indices (grouped by dst)
__device__ int   g_bsum[SCAN_NB];
__device__ int   g_boff[SCAN_NB];
__device__ float g_dis[NN];        // rsqrt(deg)   (deg = cnt+1)
__device__ float g_hs[NN * HID];   // (in @ W) * dis[node]
__device__ float g_in[NN * HID];   // layer input (tanh output of prev layer)
__device__ float g_feat[NN * 128]; // concat of 4 layer outputs

// ================= preprocessing: degree + CSR build =========================
__global__ void zero_kernel() {
    int i = blockIdx.x * 256 + threadIdx.x;
    if (i < NN) { g_cnt[i] = 0; g_fill[i] = 0; }
}
__global__ void count_kernel(const int* __restrict__ ei) {
    int e = blockIdx.x * 256 + threadIdx.x;
    if (e < NE) atomicAdd(&g_cnt[ei[NE + e]], 1);
}
// block-level inclusive scan -> exclusive rowptr (Hillis-Steele)
__global__ void scan_block_kernel() {
    __shared__ int sh[SCAN_B];
    int i = blockIdx.x * SCAN_B + threadIdx.x;
    int v = (i < NN) ? g_cnt[i] : 0;
    sh[threadIdx.x] = v;
    __syncthreads();
#pragma unroll
    for (int off = 1; off < SCAN_B; off <<= 1) {
        int t = (threadIdx.x >= off) ? sh[threadIdx.x - off] : 0;
        __syncthreads();
        sh[threadIdx.x] += t;
        __syncthreads();
    }
    if (i < NN) g_rowptr[i] = sh[threadIdx.x] - v;  // exclusive
    if (threadIdx.x == SCAN_B - 1) g_bsum[blockIdx.x] = sh[SCAN_B - 1];
}
__global__ void scan_tops_kernel() {
    if (threadIdx.x == 0) {
        int run = 0;
        for (int b = 0; b < SCAN_NB; ++b) { g_boff[b] = run; run += g_bsum[b]; }
    }
}
__global__ void scan_add_kernel() {
    int i = blockIdx.x * SCAN_B + threadIdx.x;
    if (i < NN) {
        g_rowptr[i] += g_boff[blockIdx.x];
        g_dis[i] = rsqrtf((float)(g_cnt[i] + 1));
    }
    if (i == 0) g_rowptr[NN] = NE;
}
__global__ void fill_kernel(const int* __restrict__ ei) {
    int e = blockIdx.x * 256 + threadIdx.x;
    if (e < NE) {
        int d = ei[NE + e];
        int pos = atomicAdd(&g_fill[d], 1);
        g_csr[g_rowptr[d] + pos] = ei[e];
    }
}

// ================= per-layer GEMM: g_hs = (in @ W) * dis =====================
// 256 threads = 8 warps; warp handles 4 nodes; lane = output column.
// NOTE: g_in is read INSIDE device code (never passed as a host-side arg —
// that decays to the host shadow address and silently corrupts: R3 bug).
template <int IF>
__global__ void gemm_kernel(const float* __restrict__ x,
                            const float* __restrict__ w, int use_x) {
    __shared__ float s_in[32 * IF];
    __shared__ float s_wT[32 * (IF + 4)];
    const float* in = use_x ? x : (const float*)g_in;
    int tid = threadIdx.x;
    int node0 = blockIdx.x * 32;
    for (int i = tid; i < 32 * IF; i += 256)
        s_in[i] = in[node0 * IF + i];
    // transpose W [IF,32] -> s_wT[col][k], row padded to IF+4
    for (int i = tid; i < IF * 32; i += 256) {
        int k = i >> 5, c = i & 31;
        s_wT[c * (IF + 4) + k] = w[i];
    }
    __syncthreads();

    int wi = tid >> 5, c = tid & 31;
    float acc0 = 0.f, acc1 = 0.f, acc2 = 0.f, acc3 = 0.f;
    const float4* wv4 = (const float4*)&s_wT[c * (IF + 4)];
    const float4* x0 = (const float4*)&s_in[(wi * 4 + 0) * IF];
    const float4* x1 = (const float4*)&s_in[(wi * 4 + 1) * IF];
    const float4* x2 = (const float4*)&s_in[(wi * 4 + 2) * IF];
    const float4* x3 = (const float4*)&s_in[(wi * 4 + 3) * IF];
#pragma unroll
    for (int k4 = 0; k4 < IF / 4; ++k4) {
        float4 wv = wv4[k4];
        float4 a = x0[k4];
        acc0 += wv.x * a.x + wv.y * a.y + wv.z * a.z + wv.w * a.w;
        a = x1[k4];
        acc1 += wv.x * a.x + wv.y * a.y + wv.z * a.z + wv.w * a.w;
        a = x2[k4];
        acc2 += wv.x * a.x + wv.y * a.y + wv.z * a.z + wv.w * a.w;
        a = x3[k4];
        acc3 += wv.x * a.x + wv.y * a.y + wv.z * a.z + wv.w * a.w;
    }
    int n = node0 + wi * 4;
    g_hs[(n + 0) * 32 + c] = acc0 * g_dis[n + 0];
    g_hs[(n + 1) * 32 + c] = acc1 * g_dis[n + 1];
    g_hs[(n + 2) * 32 + c] = acc2 * g_dis[n + 2];
    g_hs[(n + 3) * 32 + c] = acc3 * g_dis[n + 3];
}

// ========== aggregation (CSR gather, no atomics) + tanh + feat write =========
__global__ void agg_kernel(const float* __restrict__ b, int layer) {
    int t = blockIdx.x * 256 + threadIdx.x;
    int n = t >> 5;
    int lane = t & 31;
    if (n >= NN) return;
    float acc0 = g_hs[n * 32 + lane];   // self-loop term (hs[d])
    float acc1 = 0.f;
    int p0 = g_rowptr[n], p1 = g_rowptr[n + 1];
    for (int j = p0; j < p1; j += 32) {
        int idx = (j + lane < p1) ? g_csr[j + lane] : 0;
        int cnt = min(32, p1 - j);
        int k = 0;
        for (; k + 4 <= cnt; k += 4) {
            int s0 = __shfl_sync(0xffffffffu, idx, k);
            int s1 = __shfl_sync(0xffffffffu, idx, k + 1);
            int s2 = __shfl_sync(0xffffffffu, idx, k + 2);
            int s3 = __shfl_sync(0xffffffffu, idx, k + 3);
            acc0 += g_hs[s0 * 32 + lane];
            acc1 += g_hs[s1 * 32 + lane];
            acc0 += g_hs[s2 * 32 + lane];
            acc1 += g_hs[s3 * 32 + lane];
        }
        for (; k < cnt; ++k) {
            int s = __shfl_sync(0xffffffffu, idx, k);
            acc0 += g_hs[s * 32 + lane];
        }
    }
    float v = tanhf(g_dis[n] * (acc0 + acc1) + b[lane]);
    g_in[n * 32 + lane] = v;
    g_feat[n * 128 + layer * 32 + lane] = v;
}

// ---------------- head: sort-pool + conv1 + maxpool + conv2 + fc1 + fc2 -----
__global__ void head_kernel(const float* __restrict__ c1w, const float* __restrict__ c1b,
                            const float* __restrict__ c2w, const float* __restrict__ c2b,
                            const float* __restrict__ f1w, const float* __restrict__ f1b,
                            const float* __restrict__ f2w, const float* __restrict__ f2b,
                            float* __restrict__ out) {
    __shared__ float s_last[NPG];
    __shared__ int   s_ord[KTOP];
    __shared__ float s_top[KTOP * 128];
    __shared__ float s_y[16 * KTOP];
    __shared__ float s_p[16 * 17];
    __shared__ float s_z[32 * 13];
    __shared__ float s_f[128];
    __shared__ float s_red[128];

    int g = blockIdx.x;
    int tid = threadIdx.x;
    int base = g * NPG;

    if (tid < NPG) s_last[tid] = g_feat[(base + tid) * 128 + 127];
    __syncthreads();

    // stable rank (descending; ties -> lower index first), matches argsort(-x)
    if (tid < NPG) {
        float v = s_last[tid];
        int rank = 0;
#pragma unroll 4
        for (int j = 0; j < NPG; ++j) {
            float vj = s_last[j];
            rank += (vj > v) || (vj == v && j < tid);
        }
        if (rank < KTOP) s_ord[rank] = tid;
    }
    __syncthreads();

    for (int t = tid; t < KTOP * 128; t += 128) {
        int k = t >> 7, c = t & 127;
        s_top[t] = g_feat[(base + s_ord[k]) * 128 + c];
    }
    __syncthreads();

    // conv1 (1x1) + relu
    for (int t = tid; t < 16 * KTOP; t += 128) {
        int o = t / KTOP, k = t - o * KTOP;
        float acc = c1b[o];
        const float* wr = &c1w[o * 128];
        const float* tr = &s_top[k * 128];
#pragma unroll 8
        for (int c = 0; c < 128; ++c) acc += wr[c] * tr[c];
        s_y[o * KTOP + k] = fmaxf(acc, 0.0f);
    }
    __syncthreads();

    // maxpool1d(2): 35 -> 17
    for (int t = tid; t < 16 * 17; t += 128) {
        int o = t / 17, l = t - o * 17;
        s_p[t] = fmaxf(s_y[o * KTOP + 2 * l], s_y[o * KTOP + 2 * l + 1]);
    }
    __syncthreads();

    // conv2 (k=5, valid): 17 -> 13
    for (int t = tid; t < 32 * 13; t += 128) {
        int oc = t / 13, tt = t - oc * 13;
        float acc = c2b[oc];
        const float* wr = &c2w[oc * 80];
#pragma unroll
        for (int ic = 0; ic < 16; ++ic) {
            const float* pr = &s_p[ic * 17 + tt];
#pragma unroll
            for (int j = 0; j < 5; ++j) acc += wr[ic * 5 + j] * pr[j];
        }
        s_z[t] = fmaxf(acc, 0.0f);
    }
    __syncthreads();

    // fc1: 416 -> 128, relu
    {
        float acc = f1b[tid];
        const float* wr = &f1w[tid * 416];
#pragma unroll 8
        for (int v = 0; v < 416; ++v) acc += wr[v] * s_z[v];
        s_f[tid] = fmaxf(acc, 0.0f);
    }
    __syncthreads();

    // fc2: 128 -> 1, sigmoid
    s_red[tid] = f2w[tid] * s_f[tid];
    __syncthreads();
    for (int off = 64; off > 0; off >>= 1) {
        if (tid < off) s_red[tid] += s_red[tid + off];
        __syncthreads();
    }
    if (tid == 0) {
        float z = s_red[0] + f2b[0];
        out[g] = 1.0f / (1.0f + expf(-z));
    }
}

// ---------------- launch -----------------------------------------------------
extern "C" void kernel_launch(void* const* d_in, const int* in_sizes, int n_in,
                              void* d_out, int out_size) {
    const float* x  = (const float*)d_in[0];
    const int*   ei = (const int*)d_in[1];   // int32 (JAX x64 disabled)
    const float* w[4] = {(const float*)d_in[3], (const float*)d_in[5],
                         (const float*)d_in[7], (const float*)d_in[9]};
    const float* b[4] = {(const float*)d_in[4], (const float*)d_in[6],
                         (const float*)d_in[8], (const float*)d_in[10]};
    const float* c1w = (const float*)d_in[11];
    const float* c1b = (const float*)d_in[12];
    const float* c2w = (const float*)d_in[13];
    const float* c2b = (const float*)d_in[14];
    const float* f1w = (const float*)d_in[15];
    const float* f1b = (const float*)d_in[16];
    const float* f2w = (const float*)d_in[17];
    const float* f2b = (const float*)d_in[18];
    float* out = (float*)d_out;

    const int eb = (NE + 255) / 256;

    // ---- one-time CSR build (atomics only in preprocessing) ----
    zero_kernel      <<<(NN + 255) / 256, 256>>>();
    count_kernel     <<<eb, 256>>>(ei);
    scan_block_kernel<<<SCAN_NB, SCAN_B>>>();
    scan_tops_kernel <<<1, 32>>>();
    scan_add_kernel  <<<SCAN_NB, SCAN_B>>>();
    fill_kernel      <<<eb, 256>>>(ei);

    // ---- 4 GCN layers ----
    const int gemm_blocks = NN / 32;                // 3125
    const int agg_blocks  = (NN * 32 + 255) / 256;  // 12500
    for (int layer = 0; layer < 4; ++layer) {
        if (layer == 0) gemm_kernel<128><<<gemm_blocks, 256>>>(x, w[0], 1);
        else            gemm_kernel<32> <<<gemm_blocks, 256>>>(x, w[layer], 0);
        agg_kernel<<<agg_blocks, 256>>>(b[layer], layer);
    }

    head_kernel<<<NG, 128>>>(c1w, c1b, c2w, c2b, f1w, f1b, f2w, f2b, out);
}

// round 5
// speedup vs baseline: 2.2494x; 1.0730x over previous
#include <cuda_runtime.h>
#include <math.h>

#define NN 100000
#define NE 3200000
#define HID 32
#define NG 1000
#define NPG 100
#define KTOP 35
#define SCAN_B 1024
#define SCAN_NB ((NN + SCAN_B - 1) / SCAN_B)   // 98

// ---------------- scratch (static device globals; no allocation) ------------
__device__ int   g_cnt[NN];        // in-degree (excl self)
__device__ int   g_fill[NN];       // absolute fill cursor (seeded = rowptr)
__device__ int   g_rowptr[NN + 1]; // CSR row pointers
__device__ int   g_csr[NE];        // CSR src indices (grouped by dst)
__device__ int   g_bsum[SCAN_NB];
__device__ int   g_boff[SCAN_NB];
__device__ float g_dis[NN];        // rsqrt(deg)   (deg = cnt+1)
__device__ __align__(16) float g_hs[NN * HID];   // (in @ W) * dis[node]
__device__ __align__(16) float g_in[NN * HID];   // layer input
__device__ __align__(16) float g_feat[NN * 128]; // concat of 4 layer outputs

// ================= preprocessing: degree + CSR build =========================
__global__ void zero_kernel() {
    int i = blockIdx.x * 256 + threadIdx.x;
    if (i < NN) g_cnt[i] = 0;
}
__global__ void count_kernel(const int* __restrict__ ei) {
    int e = blockIdx.x * 256 + threadIdx.x;
    if (e < NE) atomicAdd(&g_cnt[ei[NE + e]], 1);
}
// block-level inclusive scan -> exclusive rowptr (Hillis-Steele)
__global__ void scan_block_kernel() {
    __shared__ int sh[SCAN_B];
    int i = blockIdx.x * SCAN_B + threadIdx.x;
    int v = (i < NN) ? g_cnt[i] : 0;
    sh[threadIdx.x] = v;
    __syncthreads();
#pragma unroll
    for (int off = 1; off < SCAN_B; off <<= 1) {
        int t = (threadIdx.x >= off) ? sh[threadIdx.x - off] : 0;
        __syncthreads();
        sh[threadIdx.x] += t;
        __syncthreads();
    }
    if (i < NN) g_rowptr[i] = sh[threadIdx.x] - v;  // exclusive
    if (threadIdx.x == SCAN_B - 1) g_bsum[blockIdx.x] = sh[SCAN_B - 1];
}
// scan the 98 block sums with one 128-thread block
__global__ void scan_tops_kernel() {
    __shared__ int sh[128];
    int i = threadIdx.x;
    int v = (i < SCAN_NB) ? g_bsum[i] : 0;
    sh[i] = v;
    __syncthreads();
#pragma unroll
    for (int off = 1; off < 128; off <<= 1) {
        int t = (i >= off) ? sh[i - off] : 0;
        __syncthreads();
        sh[i] += t;
        __syncthreads();
    }
    if (i < SCAN_NB) g_boff[i] = sh[i] - v;  // exclusive
}
__global__ void scan_add_kernel() {
    int i = blockIdx.x * SCAN_B + threadIdx.x;
    if (i < NN) {
        int rp = g_rowptr[i] + g_boff[blockIdx.x];
        g_rowptr[i] = rp;
        g_fill[i] = rp;                       // seed fill cursor
        g_dis[i] = rsqrtf((float)(g_cnt[i] + 1));
    }
    if (i == 0) g_rowptr[NN] = NE;
}
__global__ void fill_kernel(const int* __restrict__ ei) {
    int e = blockIdx.x * 256 + threadIdx.x;
    if (e < NE) {
        int d = ei[NE + e];
        int pos = atomicAdd(&g_fill[d], 1);  // absolute position
        g_csr[pos] = ei[e];
    }
}

// ================= per-layer GEMM: g_hs = (in @ W) * dis =====================
// 256 threads = 8 warps; warp handles 4 nodes; lane = output column.
// g_in is read INSIDE device code (never passed as a host-side arg).
template <int IF>
__global__ void gemm_kernel(const float* __restrict__ x,
                            const float* __restrict__ w, int use_x) {
    __shared__ float s_in[32 * IF];
    __shared__ float s_wT[32 * (IF + 4)];
    const float* in = use_x ? x : (const float*)g_in;
    int tid = threadIdx.x;
    int node0 = blockIdx.x * 32;
    for (int i = tid; i < 32 * IF; i += 256)
        s_in[i] = in[node0 * IF + i];
    for (int i = tid; i < IF * 32; i += 256) {
        int k = i >> 5, c = i & 31;
        s_wT[c * (IF + 4) + k] = w[i];
    }
    __syncthreads();

    int wi = tid >> 5, c = tid & 31;
    float acc0 = 0.f, acc1 = 0.f, acc2 = 0.f, acc3 = 0.f;
    const float4* wv4 = (const float4*)&s_wT[c * (IF + 4)];
    const float4* x0 = (const float4*)&s_in[(wi * 4 + 0) * IF];
    const float4* x1 = (const float4*)&s_in[(wi * 4 + 1) * IF];
    const float4* x2 = (const float4*)&s_in[(wi * 4 + 2) * IF];
    const float4* x3 = (const float4*)&s_in[(wi * 4 + 3) * IF];
#pragma unroll
    for (int k4 = 0; k4 < IF / 4; ++k4) {
        float4 wv = wv4[k4];
        float4 a = x0[k4];
        acc0 += wv.x * a.x + wv.y * a.y + wv.z * a.z + wv.w * a.w;
        a = x1[k4];
        acc1 += wv.x * a.x + wv.y * a.y + wv.z * a.z + wv.w * a.w;
        a = x2[k4];
        acc2 += wv.x * a.x + wv.y * a.y + wv.z * a.z + wv.w * a.w;
        a = x3[k4];
        acc3 += wv.x * a.x + wv.y * a.y + wv.z * a.z + wv.w * a.w;
    }
    int n = node0 + wi * 4;
    g_hs[(n + 0) * 32 + c] = acc0 * g_dis[n + 0];
    g_hs[(n + 1) * 32 + c] = acc1 * g_dis[n + 1];
    g_hs[(n + 2) * 32 + c] = acc2 * g_dis[n + 2];
    g_hs[(n + 3) * 32 + c] = acc3 * g_dis[n + 3];
}

// ========== aggregation v2: 4 nodes/warp, lane = float4 of channels ==========
// pre[d] = dis[d] * (hs[d] + sum_{s in N(d)} hs[s]);  out = tanh(pre + b)
__global__ void agg_kernel(const float* __restrict__ b, int layer) {
    int t = blockIdx.x * 256 + threadIdx.x;
    int warp = t >> 5;
    int lane = threadIdx.x & 31;
    int group = lane >> 3;        // 0..3 : node within warp
    int sub = lane & 7;           // 0..7 : float4 index within 32-ch row
    int n = warp * 4 + group;     // NN = 100000 divisible by 4
    if (n >= NN) return;

    const float4* hs4 = (const float4*)g_hs;
    float4 acc = hs4[n * 8 + sub];              // self-loop term
    int p0 = g_rowptr[n];
    int deg = g_rowptr[n + 1] - p0;
    int maxdeg = __reduce_max_sync(0xffffffffu, deg);

    for (int j = 0; j < maxdeg; j += 8) {
        int idx = (j + sub < deg) ? g_csr[p0 + j + sub] : 0;
#pragma unroll
        for (int k = 0; k < 8; ++k) {
            int s = __shfl_sync(0xffffffffu, idx, (group << 3) + k);
            if (j + k < deg) {
                float4 v = hs4[s * 8 + sub];
                acc.x += v.x; acc.y += v.y; acc.z += v.z; acc.w += v.w;
            }
        }
    }

    float dn = g_dis[n];
    float4 bb = ((const float4*)b)[sub];
    float4 o;
    o.x = tanhf(dn * acc.x + bb.x);
    o.y = tanhf(dn * acc.y + bb.y);
    o.z = tanhf(dn * acc.z + bb.z);
    o.w = tanhf(dn * acc.w + bb.w);
    ((float4*)g_in)[n * 8 + sub] = o;
    ((float4*)g_feat)[n * 32 + layer * 8 + sub] = o;
}

// ---------------- head: sort-pool + conv1 + maxpool + conv2 + fc1 + fc2 -----
__global__ void head_kernel(const float* __restrict__ c1w, const float* __restrict__ c1b,
                            const float* __restrict__ c2w, const float* __restrict__ c2b,
                            const float* __restrict__ f1w, const float* __restrict__ f1b,
                            const float* __restrict__ f2w, const float* __restrict__ f2b,
                            float* __restrict__ out) {
    __shared__ float s_last[NPG];
    __shared__ int   s_ord[KTOP];
    __shared__ float s_top[KTOP * 128];
    __shared__ float s_y[16 * KTOP];
    __shared__ float s_p[16 * 17];
    __shared__ float s_z[32 * 13];
    __shared__ float s_f[128];
    __shared__ float s_red[128];

    int g = blockIdx.x;
    int tid = threadIdx.x;
    int base = g * NPG;

    if (tid < NPG) s_last[tid] = g_feat[(base + tid) * 128 + 127];
    __syncthreads();

    // stable rank (descending; ties -> lower index first), matches argsort(-x)
    if (tid < NPG) {
        float v = s_last[tid];
        int rank = 0;
#pragma unroll 4
        for (int j = 0; j < NPG; ++j) {
            float vj = s_last[j];
            rank += (vj > v) || (vj == v && j < tid);
        }
        if (rank < KTOP) s_ord[rank] = tid;
    }
    __syncthreads();

    for (int t = tid; t < KTOP * 128; t += 128) {
        int k = t >> 7, c = t & 127;
        s_top[t] = g_feat[(base + s_ord[k]) * 128 + c];
    }
    __syncthreads();

    // conv1 (1x1) + relu
    for (int t = tid; t < 16 * KTOP; t += 128) {
        int o = t / KTOP, k = t - o * KTOP;
        float acc = c1b[o];
        const float* wr = &c1w[o * 128];
        const float* tr = &s_top[k * 128];
#pragma unroll 8
        for (int c = 0; c < 128; ++c) acc += wr[c] * tr[c];
        s_y[o * KTOP + k] = fmaxf(acc, 0.0f);
    }
    __syncthreads();

    // maxpool1d(2): 35 -> 17
    for (int t = tid; t < 16 * 17; t += 128) {
        int o = t / 17, l = t - o * 17;
        s_p[t] = fmaxf(s_y[o * KTOP + 2 * l], s_y[o * KTOP + 2 * l + 1]);
    }
    __syncthreads();

    // conv2 (k=5, valid): 17 -> 13
    for (int t = tid; t < 32 * 13; t += 128) {
        int oc = t / 13, tt = t - oc * 13;
        float acc = c2b[oc];
        const float* wr = &c2w[oc * 80];
#pragma unroll
        for (int ic = 0; ic < 16; ++ic) {
            const float* pr = &s_p[ic * 17 + tt];
#pragma unroll
            for (int j = 0; j < 5; ++j) acc += wr[ic * 5 + j] * pr[j];
        }
        s_z[t] = fmaxf(acc, 0.0f);
    }
    __syncthreads();

    // fc1: 416 -> 128, relu
    {
        float acc = f1b[tid];
        const float* wr = &f1w[tid * 416];
#pragma unroll 8
        for (int v = 0; v < 416; ++v) acc += wr[v] * s_z[v];
        s_f[tid] = fmaxf(acc, 0.0f);
    }
    __syncthreads();

    // fc2: 128 -> 1, sigmoid
    s_red[tid] = f2w[tid] * s_f[tid];
    __syncthreads();
    for (int off = 64; off > 0; off >>= 1) {
        if (tid < off) s_red[tid] += s_red[tid + off];
        __syncthreads();
    }
    if (tid == 0) {
        float z = s_red[0] + f2b[0];
        out[g] = 1.0f / (1.0f + expf(-z));
    }
}

// ---------------- launch -----------------------------------------------------
extern "C" void kernel_launch(void* const* d_in, const int* in_sizes, int n_in,
                              void* d_out, int out_size) {
    const float* x  = (const float*)d_in[0];
    const int*   ei = (const int*)d_in[1];   // int32 (JAX x64 disabled)
    const float* w[4] = {(const float*)d_in[3], (const float*)d_in[5],
                         (const float*)d_in[7], (const float*)d_in[9]};
    const float* b[4] = {(const float*)d_in[4], (const float*)d_in[6],
                         (const float*)d_in[8], (const float*)d_in[10]};
    const float* c1w = (const float*)d_in[11];
    const float* c1b = (const float*)d_in[12];
    const float* c2w = (const float*)d_in[13];
    const float* c2b = (const float*)d_in[14];
    const float* f1w = (const float*)d_in[15];
    const float* f1b = (const float*)d_in[16];
    const float* f2w = (const float*)d_in[17];
    const float* f2b = (const float*)d_in[18];
    float* out = (float*)d_out;

    const int eb = (NE + 255) / 256;

    // ---- one-time CSR build (atomics only in preprocessing) ----
    zero_kernel      <<<(NN + 255) / 256, 256>>>();
    count_kernel     <<<eb, 256>>>(ei);
    scan_block_kernel<<<SCAN_NB, SCAN_B>>>();
    scan_tops_kernel <<<1, 128>>>();
    scan_add_kernel  <<<SCAN_NB, SCAN_B>>>();
    fill_kernel      <<<eb, 256>>>(ei);

    // ---- 4 GCN layers ----
    const int gemm_blocks = NN / 32;            // 3125
    const int agg_blocks  = NN / 32;            // 3125 (32 nodes per 256-thr block)
    for (int layer = 0; layer < 4; ++layer) {
        if (layer == 0) gemm_kernel<128><<<gemm_blocks, 256>>>(x, w[0], 1);
        else            gemm_kernel<32> <<<gemm_blocks, 256>>>(x, w[layer], 0);
        agg_kernel<<<agg_blocks, 256>>>(b[layer], layer);
    }

    head_kernel<<<NG, 128>>>(c1w, c1b, c2w, c2b, f1w, f1b, f2w, f2b, out);
}

// round 6
// speedup vs baseline: 2.2671x; 1.0079x over previous
#include <cuda_runtime.h>
#include <math.h>

#define NN 100000
#define NE 3200000
#define HID 32
#define NG 1000
#define NPG 100
#define KTOP 35
#define SCAN_B 1024
#define SCAN_NB ((NN + SCAN_B - 1) / SCAN_B)   // 98

// ---------------- scratch (static device globals; no allocation) ------------
__device__ int   g_cnt[NN];
__device__ int   g_fill[NN];
__device__ int   g_rowptr[NN + 1];
__device__ int   g_csr[NE];
__device__ int   g_bsum[SCAN_NB];
__device__ int   g_boff[SCAN_NB];
__device__ float g_dis[NN];                      // rsqrt(deg), deg = cnt+1
__device__ __align__(16) float g_hsA[NN * HID];  // ping
__device__ __align__(16) float g_hsB[NN * HID];  // pong
__device__ __align__(16) float g_feat[NN * 128];

// ================= preprocessing: degree + CSR build =========================
__global__ void zero_kernel() {
    int i = blockIdx.x * 256 + threadIdx.x;
    if (i < NN) g_cnt[i] = 0;
}
__global__ void count_kernel(const int* __restrict__ ei) {
    int e = blockIdx.x * 256 + threadIdx.x;
    if (e < NE) atomicAdd(&g_cnt[ei[NE + e]], 1);
}
__global__ void scan_block_kernel() {
    __shared__ int sh[SCAN_B];
    int i = blockIdx.x * SCAN_B + threadIdx.x;
    int v = (i < NN) ? g_cnt[i] : 0;
    sh[threadIdx.x] = v;
    __syncthreads();
#pragma unroll
    for (int off = 1; off < SCAN_B; off <<= 1) {
        int t = (threadIdx.x >= off) ? sh[threadIdx.x - off] : 0;
        __syncthreads();
        sh[threadIdx.x] += t;
        __syncthreads();
    }
    if (i < NN) g_rowptr[i] = sh[threadIdx.x] - v;  // exclusive
    if (threadIdx.x == SCAN_B - 1) g_bsum[blockIdx.x] = sh[SCAN_B - 1];
}
__global__ void scan_tops_kernel() {
    __shared__ int sh[128];
    int i = threadIdx.x;
    int v = (i < SCAN_NB) ? g_bsum[i] : 0;
    sh[i] = v;
    __syncthreads();
#pragma unroll
    for (int off = 1; off < 128; off <<= 1) {
        int t = (i >= off) ? sh[i - off] : 0;
        __syncthreads();
        sh[i] += t;
        __syncthreads();
    }
    if (i < SCAN_NB) g_boff[i] = sh[i] - v;
}
__global__ void scan_add_kernel() {
    int i = blockIdx.x * SCAN_B + threadIdx.x;
    if (i < NN) {
        int rp = g_rowptr[i] + g_boff[blockIdx.x];
        g_rowptr[i] = rp;
        g_fill[i] = rp;
        g_dis[i] = rsqrtf((float)(g_cnt[i] + 1));
    }
    if (i == 0) g_rowptr[NN] = NE;
}
__global__ void fill_kernel(const int* __restrict__ ei) {
    int e = blockIdx.x * 256 + threadIdx.x;
    if (e < NE) {
        int d = ei[NE + e];
        int pos = atomicAdd(&g_fill[d], 1);
        g_csr[pos] = ei[e];
    }
}

// ============ layer-0 GEMM: g_hsA = (x @ W0) * dis  (IF=128) =================
// warp = 4 nodes, lane = output col; x rows read warp-uniform via __ldg
// (broadcast, L1-resident) -> no s_in staging, crossbar only for W.
__global__ void gemm0_kernel(const float* __restrict__ x,
                             const float* __restrict__ w) {
    __shared__ float s_wT[32 * 132];
    int tid = threadIdx.x;
    for (int i = tid; i < 128 * 32; i += 256) {
        int k = i >> 5, c = i & 31;
        s_wT[c * 132 + k] = w[i];
    }
    __syncthreads();
    int wi = tid >> 5, c = tid & 31;
    int n = blockIdx.x * 32 + wi * 4;
    float acc0 = 0.f, acc1 = 0.f, acc2 = 0.f, acc3 = 0.f;
    const float4* wv4 = (const float4*)&s_wT[c * 132];
    const float4* r0 = (const float4*)&x[(n + 0) * 128];
    const float4* r1 = (const float4*)&x[(n + 1) * 128];
    const float4* r2 = (const float4*)&x[(n + 2) * 128];
    const float4* r3 = (const float4*)&x[(n + 3) * 128];
#pragma unroll 8
    for (int k4 = 0; k4 < 32; ++k4) {
        float4 wv = wv4[k4];
        float4 a = __ldg(r0 + k4);
        acc0 += wv.x * a.x + wv.y * a.y + wv.z * a.z + wv.w * a.w;
        a = __ldg(r1 + k4);
        acc1 += wv.x * a.x + wv.y * a.y + wv.z * a.z + wv.w * a.w;
        a = __ldg(r2 + k4);
        acc2 += wv.x * a.x + wv.y * a.y + wv.z * a.z + wv.w * a.w;
        a = __ldg(r3 + k4);
        acc3 += wv.x * a.x + wv.y * a.y + wv.z * a.z + wv.w * a.w;
    }
    g_hsA[(n + 0) * 32 + c] = acc0 * g_dis[n + 0];
    g_hsA[(n + 1) * 32 + c] = acc1 * g_dis[n + 1];
    g_hsA[(n + 2) * 32 + c] = acc2 * g_dis[n + 2];
    g_hsA[(n + 3) * 32 + c] = acc3 * g_dis[n + 3];
}

// ===== fused: agg(layer) + tanh + feat write + next-layer GEMM (IF=32) =======
// block = 256 threads = 32 nodes. par selects which hs buffer to READ;
// writes the other. tanh output stays in shared for the GEMM.
__global__ void fused_kernel(const float* __restrict__ b,
                             const float* __restrict__ w,
                             int layer, int par) {
    __shared__ float s_in[32 * 32];
    __shared__ float s_wT[32 * 36];
    const float4* hs4 = (const float4*)(par ? g_hsB : g_hsA);
    float*        hso = par ? g_hsA : g_hsB;
    int tid = threadIdx.x;
    // hoist W transpose load (overlaps the gather latency below)
    for (int i = tid; i < 32 * 32; i += 256) {
        int k = i >> 5, c = i & 31;
        s_wT[c * 36 + k] = w[i];
    }
    int warp = tid >> 5, lane = tid & 31;
    int group = lane >> 3, sub = lane & 7;
    int l = warp * 4 + group;
    int n = blockIdx.x * 32 + l;

    float4 acc = hs4[n * 8 + sub];          // self-loop term
    int p0 = g_rowptr[n];
    int deg = g_rowptr[n + 1] - p0;
    int maxdeg = __reduce_max_sync(0xffffffffu, deg);
    for (int j = 0; j < maxdeg; j += 8) {
        int idx = (j + sub < deg) ? g_csr[p0 + j + sub] : 0;
#pragma unroll
        for (int k = 0; k < 8; ++k) {
            int s = __shfl_sync(0xffffffffu, idx, (group << 3) + k);
            if (j + k < deg) {
                float4 v = hs4[s * 8 + sub];
                acc.x += v.x; acc.y += v.y; acc.z += v.z; acc.w += v.w;
            }
        }
    }
    float dn = g_dis[n];
    float4 bb = ((const float4*)b)[sub];
    float4 o;
    o.x = tanhf(dn * acc.x + bb.x);
    o.y = tanhf(dn * acc.y + bb.y);
    o.z = tanhf(dn * acc.z + bb.z);
    o.w = tanhf(dn * acc.w + bb.w);
    ((float4*)g_feat)[n * 32 + layer * 8 + sub] = o;
    ((float4*)s_in)[l * 8 + sub] = o;
    __syncthreads();

    // GEMM: hs_next = (tanh_out @ Wnext) * dis
    int c = lane;
    float a0 = 0.f, a1 = 0.f, a2 = 0.f, a3 = 0.f;
    const float4* wv4 = (const float4*)&s_wT[c * 36];
    const float4* x0 = (const float4*)&s_in[(warp * 4 + 0) * 32];
    const float4* x1 = (const float4*)&s_in[(warp * 4 + 1) * 32];
    const float4* x2 = (const float4*)&s_in[(warp * 4 + 2) * 32];
    const float4* x3 = (const float4*)&s_in[(warp * 4 + 3) * 32];
#pragma unroll
    for (int k4 = 0; k4 < 8; ++k4) {
        float4 wv = wv4[k4];
        float4 a = x0[k4];
        a0 += wv.x * a.x + wv.y * a.y + wv.z * a.z + wv.w * a.w;
        a = x1[k4];
        a1 += wv.x * a.x + wv.y * a.y + wv.z * a.z + wv.w * a.w;
        a = x2[k4];
        a2 += wv.x * a.x + wv.y * a.y + wv.z * a.z + wv.w * a.w;
        a = x3[k4];
        a3 += wv.x * a.x + wv.y * a.y + wv.z * a.z + wv.w * a.w;
    }
    int nn = blockIdx.x * 32 + warp * 4;
    hso[(nn + 0) * 32 + c] = a0 * g_dis[nn + 0];
    hso[(nn + 1) * 32 + c] = a1 * g_dis[nn + 1];
    hso[(nn + 2) * 32 + c] = a2 * g_dis[nn + 2];
    hso[(nn + 3) * 32 + c] = a3 * g_dis[nn + 3];
}

// ---------------- final layer aggregation (layer 3): feat only ---------------
__global__ void agg_final_kernel(const float* __restrict__ b, int par) {
    const float4* hs4 = (const float4*)(par ? g_hsB : g_hsA);
    int t = blockIdx.x * 256 + threadIdx.x;
    int warp = t >> 5;
    int lane = threadIdx.x & 31;
    int group = lane >> 3, sub = lane & 7;
    int n = warp * 4 + group;
    if (n >= NN) return;
    float4 acc = hs4[n * 8 + sub];
    int p0 = g_rowptr[n];
    int deg = g_rowptr[n + 1] - p0;
    int maxdeg = __reduce_max_sync(0xffffffffu, deg);
    for (int j = 0; j < maxdeg; j += 8) {
        int idx = (j + sub < deg) ? g_csr[p0 + j + sub] : 0;
#pragma unroll
        for (int k = 0; k < 8; ++k) {
            int s = __shfl_sync(0xffffffffu, idx, (group << 3) + k);
            if (j + k < deg) {
                float4 v = hs4[s * 8 + sub];
                acc.x += v.x; acc.y += v.y; acc.z += v.z; acc.w += v.w;
            }
        }
    }
    float dn = g_dis[n];
    float4 bb = ((const float4*)b)[sub];
    float4 o;
    o.x = tanhf(dn * acc.x + bb.x);
    o.y = tanhf(dn * acc.y + bb.y);
    o.z = tanhf(dn * acc.z + bb.z);
    o.w = tanhf(dn * acc.w + bb.w);
    ((float4*)g_feat)[n * 32 + 3 * 8 + sub] = o;
}

// ---------------- head: sort-pool + conv1 + maxpool + conv2 + fc1 + fc2 -----
__global__ void head_kernel(const float* __restrict__ c1w, const float* __restrict__ c1b,
                            const float* __restrict__ c2w, const float* __restrict__ c2b,
                            const float* __restrict__ f1w, const float* __restrict__ f1b,
                            const float* __restrict__ f2w, const float* __restrict__ f2b,
                            float* __restrict__ out) {
    __shared__ float s_last[NPG];
    __shared__ int   s_ord[KTOP];
    __shared__ float s_top[KTOP * 128];
    __shared__ float s_y[16 * KTOP];
    __shared__ float s_p[16 * 17];
    __shared__ float s_z[32 * 13];
    __shared__ float s_f[128];
    __shared__ float s_red[128];

    int g = blockIdx.x;
    int tid = threadIdx.x;
    int base = g * NPG;

    if (tid < NPG) s_last[tid] = g_feat[(base + tid) * 128 + 127];
    __syncthreads();

    if (tid < NPG) {
        float v = s_last[tid];
        int rank = 0;
#pragma unroll 4
        for (int j = 0; j < NPG; ++j) {
            float vj = s_last[j];
            rank += (vj > v) || (vj == v && j < tid);
        }
        if (rank < KTOP) s_ord[rank] = tid;
    }
    __syncthreads();

    for (int t = tid; t < KTOP * 128; t += 128) {
        int k = t >> 7, c = t & 127;
        s_top[t] = g_feat[(base + s_ord[k]) * 128 + c];
    }
    __syncthreads();

    for (int t = tid; t < 16 * KTOP; t += 128) {
        int o = t / KTOP, k = t - o * KTOP;
        float acc = c1b[o];
        const float* wr = &c1w[o * 128];
        const float* tr = &s_top[k * 128];
#pragma unroll 8
        for (int c = 0; c < 128; ++c) acc += wr[c] * tr[c];
        s_y[o * KTOP + k] = fmaxf(acc, 0.0f);
    }
    __syncthreads();

    for (int t = tid; t < 16 * 17; t += 128) {
        int o = t / 17, l = t - o * 17;
        s_p[t] = fmaxf(s_y[o * KTOP + 2 * l], s_y[o * KTOP + 2 * l + 1]);
    }
    __syncthreads();

    for (int t = tid; t < 32 * 13; t += 128) {
        int oc = t / 13, tt = t - oc * 13;
        float acc = c2b[oc];
        const float* wr = &c2w[oc * 80];
#pragma unroll
        for (int ic = 0; ic < 16; ++ic) {
            const float* pr = &s_p[ic * 17 + tt];
#pragma unroll
            for (int j = 0; j < 5; ++j) acc += wr[ic * 5 + j] * pr[j];
        }
        s_z[t] = fmaxf(acc, 0.0f);
    }
    __syncthreads();

    {
        float acc = f1b[tid];
        const float* wr = &f1w[tid * 416];
#pragma unroll 8
        for (int v = 0; v < 416; ++v) acc += wr[v] * s_z[v];
        s_f[tid] = fmaxf(acc, 0.0f);
    }
    __syncthreads();

    s_red[tid] = f2w[tid] * s_f[tid];
    __syncthreads();
    for (int off = 64; off > 0; off >>= 1) {
        if (tid < off) s_red[tid] += s_red[tid + off];
        __syncthreads();
    }
    if (tid == 0) {
        float z = s_red[0] + f2b[0];
        out[g] = 1.0f / (1.0f + expf(-z));
    }
}

// ---------------- launch -----------------------------------------------------
extern "C" void kernel_launch(void* const* d_in, const int* in_sizes, int n_in,
                              void* d_out, int out_size) {
    const float* x  = (const float*)d_in[0];
    const int*   ei = (const int*)d_in[1];   // int32 (JAX x64 disabled)
    const float* w[4] = {(const float*)d_in[3], (const float*)d_in[5],
                         (const float*)d_in[7], (const float*)d_in[9]};
    const float* b[4] = {(const float*)d_in[4], (const float*)d_in[6],
                         (const float*)d_in[8], (const float*)d_in[10]};
    const float* c1w = (const float*)d_in[11];
    const float* c1b = (const float*)d_in[12];
    const float* c2w = (const float*)d_in[13];
    const float* c2b = (const float*)d_in[14];
    const float* f1w = (const float*)d_in[15];
    const float* f1b = (const float*)d_in[16];
    const float* f2w = (const float*)d_in[17];
    const float* f2b = (const float*)d_in[18];
    float* out = (float*)d_out;

    const int eb = (NE + 255) / 256;

    // ---- one-time CSR build ----
    zero_kernel      <<<(NN + 255) / 256, 256>>>();
    count_kernel     <<<eb, 256>>>(ei);
    scan_block_kernel<<<SCAN_NB, SCAN_B>>>();
    scan_tops_kernel <<<1, 128>>>();
    scan_add_kernel  <<<SCAN_NB, SCAN_B>>>();
    fill_kernel      <<<eb, 256>>>(ei);

    // ---- GCN layers: gemm0, then 3 fused (agg+gemm), then final agg ----
    const int nb = NN / 32;                 // 3125 blocks, 32 nodes each
    gemm0_kernel<<<nb, 256>>>(x, w[0]);                 // -> hsA
    fused_kernel<<<nb, 256>>>(b[0], w[1], 0, 0);        // read A -> write B
    fused_kernel<<<nb, 256>>>(b[1], w[2], 1, 1);        // read B -> write A
    fused_kernel<<<nb, 256>>>(b[2], w[3], 2, 0);        // read A -> write B
    agg_final_kernel<<<nb, 256>>>(b[3], 1);             // read B, feat only

    head_kernel<<<NG, 128>>>(c1w, c1b, c2w, c2b, f1w, f1b, f2w, f2b, out);
}

// round 7
// speedup vs baseline: 2.3333x; 1.0292x over previous
#include <cuda_runtime.h>
#include <math.h>

#define NN 100000
#define NE 3200000
#define HID 32
#define NG 1000
#define NPG 100
#define KTOP 35
#define SLOT 80   // max supported in-degree (Poisson(32); +8.5 sigma)

// ---------------- scratch (static device globals; no allocation) ------------
// g_cnt starts zero (module load) and is re-zeroed by cleanup_kernel at the
// end of every launch, so each replay sees a clean state.
__device__ int   g_cnt[NN];                       // in-degree (excl self)
__device__ int   g_slots[NN * SLOT];              // padded adjacency (src ids)
__device__ float g_dis[NN];                       // rsqrt(deg), deg = cnt+1
__device__ __align__(16) float g_hsA[NN * HID];   // ping
__device__ __align__(16) float g_hsB[NN * HID];   // pong
__device__ __align__(16) float g_feat[NN * 128];

__device__ __forceinline__ float fast_tanh(float x) {
    float t = __expf(2.0f * x);
    return 1.0f - __fdividef(2.0f, t + 1.0f);
}

// ========== single-pass CSR build: degree + padded adjacency ================
__global__ void fill_kernel(const int* __restrict__ ei) {
    int e = blockIdx.x * 256 + threadIdx.x;
    if (e < NE) {
        int d = ei[NE + e];
        int pos = atomicAdd(&g_cnt[d], 1);
        if (pos < SLOT) g_slots[d * SLOT + pos] = ei[e];
    }
}
__global__ void deg_kernel() {
    int i = blockIdx.x * 256 + threadIdx.x;
    if (i < NN) g_dis[i] = rsqrtf((float)(g_cnt[i] + 1));
}
__global__ void cleanup_kernel() {
    int i = blockIdx.x * 256 + threadIdx.x;
    if (i < NN) g_cnt[i] = 0;
}

// ============ layer-0 GEMM: g_hsA = (x @ W0) * dis  (IF=128) =================
// warp = 4 nodes, lane = output col; x rows read warp-uniform via __ldg.
__global__ void gemm0_kernel(const float* __restrict__ x,
                             const float* __restrict__ w) {
    __shared__ float s_wT[32 * 132];
    int tid = threadIdx.x;
    for (int i = tid; i < 128 * 32; i += 256) {
        int k = i >> 5, c = i & 31;
        s_wT[c * 132 + k] = w[i];
    }
    __syncthreads();
    int wi = tid >> 5, c = tid & 31;
    int n = blockIdx.x * 32 + wi * 4;
    float acc0 = 0.f, acc1 = 0.f, acc2 = 0.f, acc3 = 0.f;
    const float4* wv4 = (const float4*)&s_wT[c * 132];
    const float4* r0 = (const float4*)&x[(n + 0) * 128];
    const float4* r1 = (const float4*)&x[(n + 1) * 128];
    const float4* r2 = (const float4*)&x[(n + 2) * 128];
    const float4* r3 = (const float4*)&x[(n + 3) * 128];
#pragma unroll 8
    for (int k4 = 0; k4 < 32; ++k4) {
        float4 wv = wv4[k4];
        float4 a = __ldg(r0 + k4);
        acc0 += wv.x * a.x + wv.y * a.y + wv.z * a.z + wv.w * a.w;
        a = __ldg(r1 + k4);
        acc1 += wv.x * a.x + wv.y * a.y + wv.z * a.z + wv.w * a.w;
        a = __ldg(r2 + k4);
        acc2 += wv.x * a.x + wv.y * a.y + wv.z * a.z + wv.w * a.w;
        a = __ldg(r3 + k4);
        acc3 += wv.x * a.x + wv.y * a.y + wv.z * a.z + wv.w * a.w;
    }
    g_hsA[(n + 0) * 32 + c] = acc0 * g_dis[n + 0];
    g_hsA[(n + 1) * 32 + c] = acc1 * g_dis[n + 1];
    g_hsA[(n + 2) * 32 + c] = acc2 * g_dis[n + 2];
    g_hsA[(n + 3) * 32 + c] = acc3 * g_dis[n + 3];
}

// ===== fused: agg(layer) + tanh + feat write + next-layer GEMM (IF=32) =======
// block = 256 threads = 32 nodes; 4 nodes/warp, lane = float4 of channels.
__global__ void fused_kernel(const float* __restrict__ b,
                             const float* __restrict__ w,
                             int layer, int par) {
    __shared__ float s_in[32 * 32];
    __shared__ float s_wT[32 * 36];
    const float4* hs4 = (const float4*)(par ? g_hsB : g_hsA);
    float*        hso = par ? g_hsA : g_hsB;
    int tid = threadIdx.x;
    for (int i = tid; i < 32 * 32; i += 256) {   // hoisted W transpose
        int k = i >> 5, c = i & 31;
        s_wT[c * 36 + k] = w[i];
    }
    int warp = tid >> 5, lane = tid & 31;
    int group = lane >> 3, sub = lane & 7;
    int l = warp * 4 + group;
    int n = blockIdx.x * 32 + l;

    float4 acc = hs4[n * 8 + sub];               // self-loop term
    int deg = g_cnt[n];
    int base = n * SLOT;
    int maxdeg = __reduce_max_sync(0xffffffffu, deg);
    for (int j = 0; j < maxdeg; j += 8) {
        int idx = (j + sub < deg) ? g_slots[base + j + sub] : 0;
#pragma unroll
        for (int k = 0; k < 8; ++k) {
            int s = __shfl_sync(0xffffffffu, idx, (group << 3) + k);
            if (j + k < deg) {
                float4 v = hs4[s * 8 + sub];
                acc.x += v.x; acc.y += v.y; acc.z += v.z; acc.w += v.w;
            }
        }
    }
    float dn = g_dis[n];
    float4 bb = ((const float4*)b)[sub];
    float4 o;
    o.x = fast_tanh(dn * acc.x + bb.x);
    o.y = fast_tanh(dn * acc.y + bb.y);
    o.z = fast_tanh(dn * acc.z + bb.z);
    o.w = fast_tanh(dn * acc.w + bb.w);
    ((float4*)g_feat)[n * 32 + layer * 8 + sub] = o;
    ((float4*)s_in)[l * 8 + sub] = o;
    __syncthreads();

    // GEMM: hs_next = (tanh_out @ Wnext) * dis
    int c = lane;
    float a0 = 0.f, a1 = 0.f, a2 = 0.f, a3 = 0.f;
    const float4* wv4 = (const float4*)&s_wT[c * 36];
    const float4* x0 = (const float4*)&s_in[(warp * 4 + 0) * 32];
    const float4* x1 = (const float4*)&s_in[(warp * 4 + 1) * 32];
    const float4* x2 = (const float4*)&s_in[(warp * 4 + 2) * 32];
    const float4* x3 = (const float4*)&s_in[(warp * 4 + 3) * 32];
#pragma unroll
    for (int k4 = 0; k4 < 8; ++k4) {
        float4 wv = wv4[k4];
        float4 a = x0[k4];
        a0 += wv.x * a.x + wv.y * a.y + wv.z * a.z + wv.w * a.w;
        a = x1[k4];
        a1 += wv.x * a.x + wv.y * a.y + wv.z * a.z + wv.w * a.w;
        a = x2[k4];
        a2 += wv.x * a.x + wv.y * a.y + wv.z * a.z + wv.w * a.w;
        a = x3[k4];
        a3 += wv.x * a.x + wv.y * a.y + wv.z * a.z + wv.w * a.w;
    }
    int nn = blockIdx.x * 32 + warp * 4;
    hso[(nn + 0) * 32 + c] = a0 * g_dis[nn + 0];
    hso[(nn + 1) * 32 + c] = a1 * g_dis[nn + 1];
    hso[(nn + 2) * 32 + c] = a2 * g_dis[nn + 2];
    hso[(nn + 3) * 32 + c] = a3 * g_dis[nn + 3];
}

// ---------------- final layer aggregation (layer 3): feat only ---------------
__global__ void agg_final_kernel(const float* __restrict__ b, int par) {
    const float4* hs4 = (const float4*)(par ? g_hsB : g_hsA);
    int t = blockIdx.x * 256 + threadIdx.x;
    int warp = t >> 5;
    int lane = threadIdx.x & 31;
    int group = lane >> 3, sub = lane & 7;
    int n = warp * 4 + group;
    if (n >= NN) return;
    float4 acc = hs4[n * 8 + sub];
    int deg = g_cnt[n];
    int base = n * SLOT;
    int maxdeg = __reduce_max_sync(0xffffffffu, deg);
    for (int j = 0; j < maxdeg; j += 8) {
        int idx = (j + sub < deg) ? g_slots[base + j + sub] : 0;
#pragma unroll
        for (int k = 0; k < 8; ++k) {
            int s = __shfl_sync(0xffffffffu, idx, (group << 3) + k);
            if (j + k < deg) {
                float4 v = hs4[s * 8 + sub];
                acc.x += v.x; acc.y += v.y; acc.z += v.z; acc.w += v.w;
            }
        }
    }
    float dn = g_dis[n];
    float4 bb = ((const float4*)b)[sub];
    float4 o;
    o.x = fast_tanh(dn * acc.x + bb.x);
    o.y = fast_tanh(dn * acc.y + bb.y);
    o.z = fast_tanh(dn * acc.z + bb.z);
    o.w = fast_tanh(dn * acc.w + bb.w);
    ((float4*)g_feat)[n * 32 + 3 * 8 + sub] = o;
}

// ---------------- head: sort-pool + conv1 + maxpool + conv2 + fc1 + fc2 -----
__global__ void head_kernel(const float* __restrict__ c1w, const float* __restrict__ c1b,
                            const float* __restrict__ c2w, const float* __restrict__ c2b,
                            const float* __restrict__ f1w, const float* __restrict__ f1b,
                            const float* __restrict__ f2w, const float* __restrict__ f2b,
                            float* __restrict__ out) {
    __shared__ float s_last[NPG];
    __shared__ int   s_ord[KTOP];
    __shared__ float s_top[KTOP * 128];
    __shared__ float s_y[16 * KTOP];
    __shared__ float s_p[16 * 17];
    __shared__ float s_z[32 * 13];
    __shared__ float s_f[128];
    __shared__ float s_red[128];

    int g = blockIdx.x;
    int tid = threadIdx.x;
    int base = g * NPG;

    if (tid < NPG) s_last[tid] = g_feat[(base + tid) * 128 + 127];
    __syncthreads();

    // stable rank (descending; ties -> lower index first), matches argsort(-x)
    if (tid < NPG) {
        float v = s_last[tid];
        int rank = 0;
#pragma unroll 4
        for (int j = 0; j < NPG; ++j) {
            float vj = s_last[j];
            rank += (vj > v) || (vj == v && j < tid);
        }
        if (rank < KTOP) s_ord[rank] = tid;
    }
    __syncthreads();

    for (int t = tid; t < KTOP * 128; t += 128) {
        int k = t >> 7, c = t & 127;
        s_top[t] = g_feat[(base + s_ord[k]) * 128 + c];
    }
    __syncthreads();

    // conv1 (1x1) + relu
    for (int t = tid; t < 16 * KTOP; t += 128) {
        int o = t / KTOP, k = t - o * KTOP;
        float acc = c1b[o];
        const float* wr = &c1w[o * 128];
        const float* tr = &s_top[k * 128];
#pragma unroll 8
        for (int c = 0; c < 128; ++c) acc += wr[c] * tr[c];
        s_y[o * KTOP + k] = fmaxf(acc, 0.0f);
    }
    __syncthreads();

    // maxpool1d(2): 35 -> 17
    for (int t = tid; t < 16 * 17; t += 128) {
        int o = t / 17, l = t - o * 17;
        s_p[t] = fmaxf(s_y[o * KTOP + 2 * l], s_y[o * KTOP + 2 * l + 1]);
    }
    __syncthreads();

    // conv2 (k=5, valid): 17 -> 13
    for (int t = tid; t < 32 * 13; t += 128) {
        int oc = t / 13, tt = t - oc * 13;
        float acc = c2b[oc];
        const float* wr = &c2w[oc * 80];
#pragma unroll
        for (int ic = 0; ic < 16; ++ic) {
            const float* pr = &s_p[ic * 17 + tt];
#pragma unroll
            for (int j = 0; j < 5; ++j) acc += wr[ic * 5 + j] * pr[j];
        }
        s_z[t] = fmaxf(acc, 0.0f);
    }
    __syncthreads();

    // fc1: 416 -> 128, relu
    {
        float acc = f1b[tid];
        const float* wr = &f1w[tid * 416];
#pragma unroll 8
        for (int v = 0; v < 416; ++v) acc += wr[v] * s_z[v];
        s_f[tid] = fmaxf(acc, 0.0f);
    }
    __syncthreads();

    // fc2: 128 -> 1, sigmoid
    s_red[tid] = f2w[tid] * s_f[tid];
    __syncthreads();
    for (int off = 64; off > 0; off >>= 1) {
        if (tid < off) s_red[tid] += s_red[tid + off];
        __syncthreads();
    }
    if (tid == 0) {
        float z = s_red[0] + f2b[0];
        out[g] = 1.0f / (1.0f + expf(-z));
    }
}

// ---------------- launch -----------------------------------------------------
extern "C" void kernel_launch(void* const* d_in, const int* in_sizes, int n_in,
                              void* d_out, int out_size) {
    const float* x  = (const float*)d_in[0];
    const int*   ei = (const int*)d_in[1];   // int32 (JAX x64 disabled)
    const float* w[4] = {(const float*)d_in[3], (const float*)d_in[5],
                         (const float*)d_in[7], (const float*)d_in[9]};
    const float* b[4] = {(const float*)d_in[4], (const float*)d_in[6],
                         (const float*)d_in[8], (const float*)d_in[10]};
    const float* c1w = (const float*)d_in[11];
    const float* c1b = (const float*)d_in[12];
    const float* c2w = (const float*)d_in[13];
    const float* c2b = (const float*)d_in[14];
    const float* f1w = (const float*)d_in[15];
    const float* f1b = (const float*)d_in[16];
    const float* f2w = (const float*)d_in[17];
    const float* f2b = (const float*)d_in[18];
    float* out = (float*)d_out;

    const int eb = (NE + 255) / 256;
    const int nb = NN / 32;                 // 3125 blocks, 32 nodes each

    // ---- one-pass adjacency build (g_cnt zeroed at end of prior launch) ----
    fill_kernel<<<eb, 256>>>(ei);
    deg_kernel <<<(NN + 255) / 256, 256>>>();

    // ---- GCN layers: gemm0, then 3 fused (agg+gemm), then final agg ----
    gemm0_kernel<<<nb, 256>>>(x, w[0]);                 // -> hsA
    fused_kernel<<<nb, 256>>>(b[0], w[1], 0, 0);        // read A -> write B
    fused_kernel<<<nb, 256>>>(b[1], w[2], 1, 1);        // read B -> write A
    fused_kernel<<<nb, 256>>>(b[2], w[3], 2, 0);        // read A -> write B
    agg_final_kernel<<<nb, 256>>>(b[3], 1);             // read B, feat only

    head_kernel<<<NG, 128>>>(c1w, c1b, c2w, c2b, f1w, f1b, f2w, f2b, out);

    // ---- reset degree counters for the next replay ----
    cleanup_kernel<<<(NN + 255) / 256, 256>>>();
}

// round 8
// speedup vs baseline: 4.4958x; 1.9268x over previous
#include <cuda_runtime.h>
#include <math.h>

#define NN 100000
#define NE 3200000
#define HID 32
#define NG 1000
#define NPG 100
#define KTOP 35
#define SLOT 80   // max supported in-degree (Poisson(32); +8.5 sigma)

// ---------------- scratch (static device globals; no allocation) ------------
__device__ int   g_cnt[NN];                       // in-degree (excl self)
__device__ int   g_slots[NN * SLOT];              // padded adjacency (src ids)
__device__ float g_dis[NN];                       // rsqrt(deg), deg = cnt+1
__device__ __align__(16) float g_hsA[NN * HID];   // ping
__device__ __align__(16) float g_hsB[NN * HID];   // pong
__device__ __align__(16) float g_feat[NN * 128];
__device__ __align__(16) float g_z[NG * 416];     // head conv output

// ========== single-pass adjacency build ======================================
__global__ void fill_kernel(const int* __restrict__ ei) {
    int e = blockIdx.x * 256 + threadIdx.x;
    if (e < NE) {
        int d = ei[NE + e];
        int pos = atomicAdd(&g_cnt[d], 1);
        if (pos < SLOT) g_slots[d * SLOT + pos] = ei[e];
    }
}
__global__ void deg_kernel() {
    int i = blockIdx.x * 256 + threadIdx.x;
    if (i < NN) g_dis[i] = rsqrtf((float)(g_cnt[i] + 1));
}
__global__ void cleanup_kernel() {
    int i = blockIdx.x * 256 + threadIdx.x;
    if (i < NN) g_cnt[i] = 0;
}

// ============ layer-0 GEMM: g_hsA = (x @ W0) * dis  (IF=128) =================
__global__ void gemm0_kernel(const float* __restrict__ x,
                             const float* __restrict__ w) {
    __shared__ float s_wT[32 * 132];
    int tid = threadIdx.x;
    for (int i = tid; i < 128 * 32; i += 256) {
        int k = i >> 5, c = i & 31;
        s_wT[c * 132 + k] = w[i];
    }
    __syncthreads();
    int wi = tid >> 5, c = tid & 31;
    int n = blockIdx.x * 32 + wi * 4;
    float acc0 = 0.f, acc1 = 0.f, acc2 = 0.f, acc3 = 0.f;
    const float4* wv4 = (const float4*)&s_wT[c * 132];
    const float4* r0 = (const float4*)&x[(n + 0) * 128];
    const float4* r1 = (const float4*)&x[(n + 1) * 128];
    const float4* r2 = (const float4*)&x[(n + 2) * 128];
    const float4* r3 = (const float4*)&x[(n + 3) * 128];
#pragma unroll 8
    for (int k4 = 0; k4 < 32; ++k4) {
        float4 wv = wv4[k4];
        float4 a = __ldg(r0 + k4);
        acc0 += wv.x * a.x + wv.y * a.y + wv.z * a.z + wv.w * a.w;
        a = __ldg(r1 + k4);
        acc1 += wv.x * a.x + wv.y * a.y + wv.z * a.z + wv.w * a.w;
        a = __ldg(r2 + k4);
        acc2 += wv.x * a.x + wv.y * a.y + wv.z * a.z + wv.w * a.w;
        a = __ldg(r3 + k4);
        acc3 += wv.x * a.x + wv.y * a.y + wv.z * a.z + wv.w * a.w;
    }
    g_hsA[(n + 0) * 32 + c] = acc0 * g_dis[n + 0];
    g_hsA[(n + 1) * 32 + c] = acc1 * g_dis[n + 1];
    g_hsA[(n + 2) * 32 + c] = acc2 * g_dis[n + 2];
    g_hsA[(n + 3) * 32 + c] = acc3 * g_dis[n + 3];
}

// ===== fused: agg(layer) + tanh + feat write + next-layer GEMM (IF=32) =======
__global__ void fused_kernel(const float* __restrict__ b,
                             const float* __restrict__ w,
                             int layer, int par) {
    __shared__ float s_in[32 * 32];
    __shared__ float s_wT[32 * 36];
    const float4* hs4 = (const float4*)(par ? g_hsB : g_hsA);
    float*        hso = par ? g_hsA : g_hsB;
    int tid = threadIdx.x;
    for (int i = tid; i < 32 * 32; i += 256) {
        int k = i >> 5, c = i & 31;
        s_wT[c * 36 + k] = w[i];
    }
    int warp = tid >> 5, lane = tid & 31;
    int group = lane >> 3, sub = lane & 7;
    int l = warp * 4 + group;
    int n = blockIdx.x * 32 + l;

    float4 acc = hs4[n * 8 + sub];               // self-loop term
    int deg = g_cnt[n];
    int base = n * SLOT;
    int maxdeg = __reduce_max_sync(0xffffffffu, deg);
    for (int j = 0; j < maxdeg; j += 8) {
        int idx = (j + sub < deg) ? g_slots[base + j + sub] : 0;
#pragma unroll
        for (int k = 0; k < 8; ++k) {
            int s = __shfl_sync(0xffffffffu, idx, (group << 3) + k);
            if (j + k < deg) {
                float4 v = hs4[s * 8 + sub];
                acc.x += v.x; acc.y += v.y; acc.z += v.z; acc.w += v.w;
            }
        }
    }
    float dn = g_dis[n];
    float4 bb = ((const float4*)b)[sub];
    float4 o;
    o.x = tanhf(dn * acc.x + bb.x);
    o.y = tanhf(dn * acc.y + bb.y);
    o.z = tanhf(dn * acc.z + bb.z);
    o.w = tanhf(dn * acc.w + bb.w);
    ((float4*)g_feat)[n * 32 + layer * 8 + sub] = o;
    ((float4*)s_in)[l * 8 + sub] = o;
    __syncthreads();

    int c = lane;
    float a0 = 0.f, a1 = 0.f, a2 = 0.f, a3 = 0.f;
    const float4* wv4 = (const float4*)&s_wT[c * 36];
    const float4* x0 = (const float4*)&s_in[(warp * 4 + 0) * 32];
    const float4* x1 = (const float4*)&s_in[(warp * 4 + 1) * 32];
    const float4* x2 = (const float4*)&s_in[(warp * 4 + 2) * 32];
    const float4* x3 = (const float4*)&s_in[(warp * 4 + 3) * 32];
#pragma unroll
    for (int k4 = 0; k4 < 8; ++k4) {
        float4 wv = wv4[k4];
        float4 a = x0[k4];
        a0 += wv.x * a.x + wv.y * a.y + wv.z * a.z + wv.w * a.w;
        a = x1[k4];
        a1 += wv.x * a.x + wv.y * a.y + wv.z * a.z + wv.w * a.w;
        a = x2[k4];
        a2 += wv.x * a.x + wv.y * a.y + wv.z * a.z + wv.w * a.w;
        a = x3[k4];
        a3 += wv.x * a.x + wv.y * a.y + wv.z * a.z + wv.w * a.w;
    }
    int nn = blockIdx.x * 32 + warp * 4;
    hso[(nn + 0) * 32 + c] = a0 * g_dis[nn + 0];
    hso[(nn + 1) * 32 + c] = a1 * g_dis[nn + 1];
    hso[(nn + 2) * 32 + c] = a2 * g_dis[nn + 2];
    hso[(nn + 3) * 32 + c] = a3 * g_dis[nn + 3];
}

// ---------------- final layer aggregation (layer 3): feat only ---------------
__global__ void agg_final_kernel(const float* __restrict__ b, int par) {
    const float4* hs4 = (const float4*)(par ? g_hsB : g_hsA);
    int t = blockIdx.x * 256 + threadIdx.x;
    int warp = t >> 5;
    int lane = threadIdx.x & 31;
    int group = lane >> 3, sub = lane & 7;
    int n = warp * 4 + group;
    if (n >= NN) return;
    float4 acc = hs4[n * 8 + sub];
    int deg = g_cnt[n];
    int base = n * SLOT;
    int maxdeg = __reduce_max_sync(0xffffffffu, deg);
    for (int j = 0; j < maxdeg; j += 8) {
        int idx = (j + sub < deg) ? g_slots[base + j + sub] : 0;
#pragma unroll
        for (int k = 0; k < 8; ++k) {
            int s = __shfl_sync(0xffffffffu, idx, (group << 3) + k);
            if (j + k < deg) {
                float4 v = hs4[s * 8 + sub];
                acc.x += v.x; acc.y += v.y; acc.z += v.z; acc.w += v.w;
            }
        }
    }
    float dn = g_dis[n];
    float4 bb = ((const float4*)b)[sub];
    float4 o;
    o.x = tanhf(dn * acc.x + bb.x);
    o.y = tanhf(dn * acc.y + bb.y);
    o.z = tanhf(dn * acc.z + bb.z);
    o.w = tanhf(dn * acc.w + bb.w);
    ((float4*)g_feat)[n * 32 + 3 * 8 + sub] = o;
}

// ========== head part 1 (per graph): sort-pool + conv1 + pool + conv2 =======
__global__ void head1_kernel(const float* __restrict__ c1w, const float* __restrict__ c1b,
                             const float* __restrict__ c2w, const float* __restrict__ c2b) {
    __shared__ float s_last[NPG];
    __shared__ int   s_ord[KTOP];
    __shared__ float s_topT[128 * 36];  // transposed: [c][k], stride 36
    __shared__ float s_y[16 * KTOP];
    __shared__ float s_p[16 * 17];

    int g = blockIdx.x;
    int tid = threadIdx.x;
    int base = g * NPG;

    if (tid < NPG) s_last[tid] = g_feat[(base + tid) * 128 + 127];
    __syncthreads();

    // stable rank (descending; ties -> lower index first) == argsort(-x)
    if (tid < NPG) {
        float v = s_last[tid];
        int rank = 0;
#pragma unroll 4
        for (int j = 0; j < NPG; ++j) {
            float vj = s_last[j];
            rank += (vj > v) || (vj == v && j < tid);
        }
        if (rank < KTOP) s_ord[rank] = tid;
    }
    __syncthreads();

    // gather top-K rows, transposed into s_topT[c*36+k]
    // consecutive threads -> consecutive c : coalesced global read
    for (int t = tid; t < KTOP * 128; t += 128) {
        int k = t >> 7, c = t & 127;
        s_topT[c * 36 + k] = g_feat[(base + s_ord[k]) * 128 + c];
    }
    __syncthreads();

    // conv1 (1x1) + relu : warp spans k -> conflict-free LDS
    for (int t = tid; t < 16 * KTOP; t += 128) {
        int o = t / KTOP, k = t - o * KTOP;
        float acc = c1b[o];
        const float* wr = &c1w[o * 128];
#pragma unroll 8
        for (int c = 0; c < 128; ++c) acc += wr[c] * s_topT[c * 36 + k];
        s_y[o * KTOP + k] = fmaxf(acc, 0.0f);
    }
    __syncthreads();

    // maxpool1d(2): 35 -> 17
    for (int t = tid; t < 16 * 17; t += 128) {
        int o = t / 17, l = t - o * 17;
        s_p[t] = fmaxf(s_y[o * KTOP + 2 * l], s_y[o * KTOP + 2 * l + 1]);
    }
    __syncthreads();

    // conv2 (k=5, valid): 17 -> 13 ; write flattened 416 to global
    for (int t = tid; t < 32 * 13; t += 128) {
        int oc = t / 13, tt = t - oc * 13;
        float acc = c2b[oc];
        const float* wr = &c2w[oc * 80];
#pragma unroll
        for (int ic = 0; ic < 16; ++ic) {
            const float* pr = &s_p[ic * 17 + tt];
#pragma unroll
            for (int j = 0; j < 5; ++j) acc += wr[ic * 5 + j] * pr[j];
        }
        g_z[g * 416 + t] = fmaxf(acc, 0.0f);
    }
}

// ========== head part 2: fc1 (batched GEMM) + relu + fc2 + sigmoid ==========
// block = 256 threads (8 warps), 8 graphs per block. Warp w computes output
// rows o = w, w+8, ..., 120 for ALL 8 graphs (weight row read once, coalesced
// float4, reused 8x). 416 = 104 float4.
__global__ void head2_kernel(const float* __restrict__ f1w, const float* __restrict__ f1b,
                             const float* __restrict__ f2w, const float* __restrict__ f2b,
                             float* __restrict__ out) {
    __shared__ float s_z[8 * 416];     // 13.3 KB
    __shared__ float s_f[8 * 128];     // fc1 outputs [graph][o]
    int tid = threadIdx.x;
    int g0 = blockIdx.x * 8;

    for (int i = tid; i < 8 * 416; i += 256)
        s_z[i] = g_z[g0 * 416 + i];
    __syncthreads();

    int warp = tid >> 5, lane = tid & 31;
    const float4* w4 = (const float4*)f1w;
    const float4* z4 = (const float4*)s_z;

    for (int o = warp; o < 128; o += 8) {
        float p0 = 0.f, p1 = 0.f, p2 = 0.f, p3 = 0.f;
        float p4 = 0.f, p5 = 0.f, p6 = 0.f, p7 = 0.f;
        for (int seg = lane; seg < 104; seg += 32) {
            float4 wv = __ldg(w4 + o * 104 + seg);
            float4 a;
            a = z4[0 * 104 + seg]; p0 += wv.x * a.x + wv.y * a.y + wv.z * a.z + wv.w * a.w;
            a = z4[1 * 104 + seg]; p1 += wv.x * a.x + wv.y * a.y + wv.z * a.z + wv.w * a.w;
            a = z4[2 * 104 + seg]; p2 += wv.x * a.x + wv.y * a.y + wv.z * a.z + wv.w * a.w;
            a = z4[3 * 104 + seg]; p3 += wv.x * a.x + wv.y * a.y + wv.z * a.z + wv.w * a.w;
            a = z4[4 * 104 + seg]; p4 += wv.x * a.x + wv.y * a.y + wv.z * a.z + wv.w * a.w;
            a = z4[5 * 104 + seg]; p5 += wv.x * a.x + wv.y * a.y + wv.z * a.z + wv.w * a.w;
            a = z4[6 * 104 + seg]; p6 += wv.x * a.x + wv.y * a.y + wv.z * a.z + wv.w * a.w;
            a = z4[7 * 104 + seg]; p7 += wv.x * a.x + wv.y * a.y + wv.z * a.z + wv.w * a.w;
        }
#pragma unroll
        for (int m = 16; m > 0; m >>= 1) {
            p0 += __shfl_xor_sync(0xffffffffu, p0, m);
            p1 += __shfl_xor_sync(0xffffffffu, p1, m);
            p2 += __shfl_xor_sync(0xffffffffu, p2, m);
            p3 += __shfl_xor_sync(0xffffffffu, p3, m);
            p4 += __shfl_xor_sync(0xffffffffu, p4, m);
            p5 += __shfl_xor_sync(0xffffffffu, p5, m);
            p6 += __shfl_xor_sync(0xffffffffu, p6, m);
            p7 += __shfl_xor_sync(0xffffffffu, p7, m);
        }
        if (lane == 0) {
            float bb = f1b[o];
            s_f[0 * 128 + o] = fmaxf(p0 + bb, 0.0f);
            s_f[1 * 128 + o] = fmaxf(p1 + bb, 0.0f);
            s_f[2 * 128 + o] = fmaxf(p2 + bb, 0.0f);
            s_f[3 * 128 + o] = fmaxf(p3 + bb, 0.0f);
            s_f[4 * 128 + o] = fmaxf(p4 + bb, 0.0f);
            s_f[5 * 128 + o] = fmaxf(p5 + bb, 0.0f);
            s_f[6 * 128 + o] = fmaxf(p6 + bb, 0.0f);
            s_f[7 * 128 + o] = fmaxf(p7 + bb, 0.0f);
        }
    }
    __syncthreads();

    // fc2: warp per graph, 128-wide dot + sigmoid
    float acc = f2w[lane]            * s_f[warp * 128 + lane]
              + f2w[lane + 32]       * s_f[warp * 128 + lane + 32]
              + f2w[lane + 64]       * s_f[warp * 128 + lane + 64]
              + f2w[lane + 96]       * s_f[warp * 128 + lane + 96];
#pragma unroll
    for (int m = 16; m > 0; m >>= 1)
        acc += __shfl_xor_sync(0xffffffffu, acc, m);
    if (lane == 0) {
        float z = acc + f2b[0];
        out[g0 + warp] = 1.0f / (1.0f + expf(-z));
    }
}

// ---------------- launch -----------------------------------------------------
extern "C" void kernel_launch(void* const* d_in, const int* in_sizes, int n_in,
                              void* d_out, int out_size) {
    const float* x  = (const float*)d_in[0];
    const int*   ei = (const int*)d_in[1];   // int32 (JAX x64 disabled)
    const float* w[4] = {(const float*)d_in[3], (const float*)d_in[5],
                         (const float*)d_in[7], (const float*)d_in[9]};
    const float* b[4] = {(const float*)d_in[4], (const float*)d_in[6],
                         (const float*)d_in[8], (const float*)d_in[10]};
    const float* c1w = (const float*)d_in[11];
    const float* c1b = (const float*)d_in[12];
    const float* c2w = (const float*)d_in[13];
    const float* c2b = (const float*)d_in[14];
    const float* f1w = (const float*)d_in[15];
    const float* f1b = (const float*)d_in[16];
    const float* f2w = (const float*)d_in[17];
    const float* f2b = (const float*)d_in[18];
    float* out = (float*)d_out;

    const int eb = (NE + 255) / 256;
    const int nb = NN / 32;                 // 3125 blocks, 32 nodes each

    fill_kernel<<<eb, 256>>>(ei);
    deg_kernel <<<(NN + 255) / 256, 256>>>();

    gemm0_kernel<<<nb, 256>>>(x, w[0]);                 // -> hsA
    fused_kernel<<<nb, 256>>>(b[0], w[1], 0, 0);        // read A -> write B
    fused_kernel<<<nb, 256>>>(b[1], w[2], 1, 1);        // read B -> write A
    fused_kernel<<<nb, 256>>>(b[2], w[3], 2, 0);        // read A -> write B
    agg_final_kernel<<<nb, 256>>>(b[3], 1);             // read B, feat only

    head1_kernel<<<NG, 128>>>(c1w, c1b, c2w, c2b);
    head2_kernel<<<NG / 8, 256>>>(f1w, f1b, f2w, f2b, out);

    cleanup_kernel<<<(NN + 255) / 256, 256>>>();
}

// round 9
// speedup vs baseline: 4.6892x; 1.0430x over previous
#include <cuda_runtime.h>
#include <math.h>

#define NN 100000
#define NE 3200000
#define HID 32
#define NG 1000
#define NPG 100
#define KTOP 35
#define SLOT 80   // max supported in-degree (Poisson(32); +8.5 sigma)

// ---------------- scratch (static device globals; no allocation) ------------
__device__ int   g_cnt[NN];                       // in-degree (excl self)
__device__ int   g_slots[NN * SLOT];              // padded adjacency (src ids)
__device__ __align__(16) float g_hsA[NN * HID];   // ping
__device__ __align__(16) float g_hsB[NN * HID];   // pong
__device__ __align__(16) float g_feat[NN * 128];
__device__ __align__(16) float g_z[NG * 416];     // head conv output

// ========== single-pass adjacency build ======================================
__global__ void fill_kernel(const int* __restrict__ ei) {
    int e = blockIdx.x * 256 + threadIdx.x;
    if (e < NE) {
        int d = ei[NE + e];
        int pos = atomicAdd(&g_cnt[d], 1);
        if (pos < SLOT) g_slots[d * SLOT + pos] = ei[e];
    }
}
__global__ void cleanup_kernel() {
    int i = blockIdx.x * 256 + threadIdx.x;
    if (i < NN) g_cnt[i] = 0;
}

// ============ layer-0 GEMM: g_hsA = (x @ W0) * rsqrt(deg)  (IF=128) ==========
__global__ void gemm0_kernel(const float* __restrict__ x,
                             const float* __restrict__ w) {
    __shared__ float s_wT[32 * 132];
    int tid = threadIdx.x;
    for (int i = tid; i < 128 * 32; i += 256) {
        int k = i >> 5, c = i & 31;
        s_wT[c * 132 + k] = w[i];
    }
    __syncthreads();
    int wi = tid >> 5, c = tid & 31;
    int n = blockIdx.x * 32 + wi * 4;
    float acc0 = 0.f, acc1 = 0.f, acc2 = 0.f, acc3 = 0.f;
    const float4* wv4 = (const float4*)&s_wT[c * 132];
    const float4* r0 = (const float4*)&x[(n + 0) * 128];
    const float4* r1 = (const float4*)&x[(n + 1) * 128];
    const float4* r2 = (const float4*)&x[(n + 2) * 128];
    const float4* r3 = (const float4*)&x[(n + 3) * 128];
#pragma unroll 8
    for (int k4 = 0; k4 < 32; ++k4) {
        float4 wv = wv4[k4];
        float4 a = __ldg(r0 + k4);
        acc0 += wv.x * a.x + wv.y * a.y + wv.z * a.z + wv.w * a.w;
        a = __ldg(r1 + k4);
        acc1 += wv.x * a.x + wv.y * a.y + wv.z * a.z + wv.w * a.w;
        a = __ldg(r2 + k4);
        acc2 += wv.x * a.x + wv.y * a.y + wv.z * a.z + wv.w * a.w;
        a = __ldg(r3 + k4);
        acc3 += wv.x * a.x + wv.y * a.y + wv.z * a.z + wv.w * a.w;
    }
    float d0 = rsqrtf((float)g_cnt[n + 0] + 1.0f);
    float d1 = rsqrtf((float)g_cnt[n + 1] + 1.0f);
    float d2 = rsqrtf((float)g_cnt[n + 2] + 1.0f);
    float d3 = rsqrtf((float)g_cnt[n + 3] + 1.0f);
    g_hsA[(n + 0) * 32 + c] = acc0 * d0;
    g_hsA[(n + 1) * 32 + c] = acc1 * d1;
    g_hsA[(n + 2) * 32 + c] = acc2 * d2;
    g_hsA[(n + 3) * 32 + c] = acc3 * d3;
}

// ===== fused: agg(layer) + tanh + feat write + next-layer GEMM (IF=32) =======
// block = 256 threads = 32 nodes; warp = 4 nodes, 8 lanes/node (float4 chans).
// GEMM is WARP-LOCAL (per-warp smem tile + __syncwarp) -> no block sync tail.
__global__ void fused_kernel(const float* __restrict__ b,
                             const float* __restrict__ w,
                             int layer, int par) {
    __shared__ float s_wT[32 * 36];
    __shared__ float s_in[8][128];     // per-warp: 4 nodes x 32 channels
    const float4* hs4 = (const float4*)(par ? g_hsB : g_hsA);
    float*        hso = par ? g_hsA : g_hsB;
    int tid = threadIdx.x;
    for (int i = tid; i < 32 * 32; i += 256) {   // stage W transpose
        int k = i >> 5, c = i & 31;
        s_wT[c * 36 + k] = w[i];
    }
    __syncthreads();                             // early, uniform arrival

    int warp = tid >> 5, lane = tid & 31;
    int group = lane >> 3, sub = lane & 7;
    int n = blockIdx.x * 32 + warp * 4 + group;

    float4 acc = hs4[n * 8 + sub];               // self-loop term
    int deg = g_cnt[n];
    int base = n * SLOT;
    int maxdeg = __reduce_max_sync(0xffffffffu, deg);
    for (int j = 0; j < maxdeg; j += 8) {
        int idx = (j + sub < deg) ? g_slots[base + j + sub] : 0;
#pragma unroll
        for (int k = 0; k < 8; ++k) {
            int s = __shfl_sync(0xffffffffu, idx, (group << 3) + k);
            if (j + k < deg) {
                float4 v = hs4[s * 8 + sub];
                acc.x += v.x; acc.y += v.y; acc.z += v.z; acc.w += v.w;
            }
        }
    }
    float dn = rsqrtf((float)deg + 1.0f);
    float4 bb = ((const float4*)b)[sub];
    float4 o;
    o.x = tanhf(dn * acc.x + bb.x);
    o.y = tanhf(dn * acc.y + bb.y);
    o.z = tanhf(dn * acc.z + bb.z);
    o.w = tanhf(dn * acc.w + bb.w);
    ((float4*)g_feat)[n * 32 + layer * 8 + sub] = o;
    ((float4*)&s_in[warp][0])[group * 8 + sub] = o;
    __syncwarp();

    // warp-local GEMM: hs_next = (tanh_out @ Wnext) * rsqrt(deg)
    int c = lane;
    float a0 = 0.f, a1 = 0.f, a2 = 0.f, a3 = 0.f;
    const float4* wv4 = (const float4*)&s_wT[c * 36];
    const float4* x0 = (const float4*)&s_in[warp][0];
    const float4* x1 = (const float4*)&s_in[warp][32];
    const float4* x2 = (const float4*)&s_in[warp][64];
    const float4* x3 = (const float4*)&s_in[warp][96];
#pragma unroll
    for (int k4 = 0; k4 < 8; ++k4) {
        float4 wv = wv4[k4];
        float4 a = x0[k4];
        a0 += wv.x * a.x + wv.y * a.y + wv.z * a.z + wv.w * a.w;
        a = x1[k4];
        a1 += wv.x * a.x + wv.y * a.y + wv.z * a.z + wv.w * a.w;
        a = x2[k4];
        a2 += wv.x * a.x + wv.y * a.y + wv.z * a.z + wv.w * a.w;
        a = x3[k4];
        a3 += wv.x * a.x + wv.y * a.y + wv.z * a.z + wv.w * a.w;
    }
    int nn = blockIdx.x * 32 + warp * 4;
    float e0 = rsqrtf((float)g_cnt[nn + 0] + 1.0f);
    float e1 = rsqrtf((float)g_cnt[nn + 1] + 1.0f);
    float e2 = rsqrtf((float)g_cnt[nn + 2] + 1.0f);
    float e3 = rsqrtf((float)g_cnt[nn + 3] + 1.0f);
    hso[(nn + 0) * 32 + c] = a0 * e0;
    hso[(nn + 1) * 32 + c] = a1 * e1;
    hso[(nn + 2) * 32 + c] = a2 * e2;
    hso[(nn + 3) * 32 + c] = a3 * e3;
}

// ---------------- final layer aggregation (layer 3): feat only ---------------
__global__ void agg_final_kernel(const float* __restrict__ b, int par) {
    const float4* hs4 = (const float4*)(par ? g_hsB : g_hsA);
    int t = blockIdx.x * 256 + threadIdx.x;
    int warp = t >> 5;
    int lane = threadIdx.x & 31;
    int group = lane >> 3, sub = lane & 7;
    int n = warp * 4 + group;
    if (n >= NN) return;
    float4 acc = hs4[n * 8 + sub];
    int deg = g_cnt[n];
    int base = n * SLOT;
    int maxdeg = __reduce_max_sync(0xffffffffu, deg);
    for (int j = 0; j < maxdeg; j += 8) {
        int idx = (j + sub < deg) ? g_slots[base + j + sub] : 0;
#pragma unroll
        for (int k = 0; k < 8; ++k) {
            int s = __shfl_sync(0xffffffffu, idx, (group << 3) + k);
            if (j + k < deg) {
                float4 v = hs4[s * 8 + sub];
                acc.x += v.x; acc.y += v.y; acc.z += v.z; acc.w += v.w;
            }
        }
    }
    float dn = rsqrtf((float)deg + 1.0f);
    float4 bb = ((const float4*)b)[sub];
    float4 o;
    o.x = tanhf(dn * acc.x + bb.x);
    o.y = tanhf(dn * acc.y + bb.y);
    o.z = tanhf(dn * acc.z + bb.z);
    o.w = tanhf(dn * acc.w + bb.w);
    ((float4*)g_feat)[n * 32 + 3 * 8 + sub] = o;
}

// ========== head part 1 (per graph): sort-pool + conv1 + pool + conv2 =======
__global__ void head1_kernel(const float* __restrict__ c1w, const float* __restrict__ c1b,
                             const float* __restrict__ c2w, const float* __restrict__ c2b) {
    __shared__ float s_last[NPG];
    __shared__ int   s_ord[KTOP];
    __shared__ float s_topT[128 * 36];  // transposed: [c][k], stride 36
    __shared__ float s_y[16 * KTOP];
    __shared__ float s_p[16 * 17];

    int g = blockIdx.x;
    int tid = threadIdx.x;
    int base = g * NPG;

    if (tid < NPG) s_last[tid] = g_feat[(base + tid) * 128 + 127];
    __syncthreads();

    // stable rank (descending; ties -> lower index first) == argsort(-x)
    if (tid < NPG) {
        float v = s_last[tid];
        int rank = 0;
#pragma unroll 4
        for (int j = 0; j < NPG; ++j) {
            float vj = s_last[j];
            rank += (vj > v) || (vj == v && j < tid);
        }
        if (rank < KTOP) s_ord[rank] = tid;
    }
    __syncthreads();

    for (int t = tid; t < KTOP * 128; t += 128) {
        int k = t >> 7, c = t & 127;
        s_topT[c * 36 + k] = g_feat[(base + s_ord[k]) * 128 + c];
    }
    __syncthreads();

    // conv1 (1x1) + relu : warp spans k -> conflict-free LDS
    for (int t = tid; t < 16 * KTOP; t += 128) {
        int o = t / KTOP, k = t - o * KTOP;
        float acc = c1b[o];
        const float* wr = &c1w[o * 128];
#pragma unroll 8
        for (int c = 0; c < 128; ++c) acc += wr[c] * s_topT[c * 36 + k];
        s_y[o * KTOP + k] = fmaxf(acc, 0.0f);
    }
    __syncthreads();

    for (int t = tid; t < 16 * 17; t += 128) {
        int o = t / 17, l = t - o * 17;
        s_p[t] = fmaxf(s_y[o * KTOP + 2 * l], s_y[o * KTOP + 2 * l + 1]);
    }
    __syncthreads();

    for (int t = tid; t < 32 * 13; t += 128) {
        int oc = t / 13, tt = t - oc * 13;
        float acc = c2b[oc];
        const float* wr = &c2w[oc * 80];
#pragma unroll
        for (int ic = 0; ic < 16; ++ic) {
            const float* pr = &s_p[ic * 17 + tt];
#pragma unroll
            for (int j = 0; j < 5; ++j) acc += wr[ic * 5 + j] * pr[j];
        }
        g_z[g * 416 + t] = fmaxf(acc, 0.0f);
    }
}

// ========== head part 2: fc1 (batched GEMM) + relu + fc2 + sigmoid ==========
__global__ void head2_kernel(const float* __restrict__ f1w, const float* __restrict__ f1b,
                             const float* __restrict__ f2w, const float* __restrict__ f2b,
                             float* __restrict__ out) {
    __shared__ float s_z[8 * 416];
    __shared__ float s_f[8 * 128];
    int tid = threadIdx.x;
    int g0 = blockIdx.x * 8;

    for (int i = tid; i < 8 * 416; i += 256)
        s_z[i] = g_z[g0 * 416 + i];
    __syncthreads();

    int warp = tid >> 5, lane = tid & 31;
    const float4* w4 = (const float4*)f1w;
    const float4* z4 = (const float4*)s_z;

    for (int o = warp; o < 128; o += 8) {
        float p0 = 0.f, p1 = 0.f, p2 = 0.f, p3 = 0.f;
        float p4 = 0.f, p5 = 0.f, p6 = 0.f, p7 = 0.f;
        for (int seg = lane; seg < 104; seg += 32) {
            float4 wv = __ldg(w4 + o * 104 + seg);
            float4 a;
            a = z4[0 * 104 + seg]; p0 += wv.x * a.x + wv.y * a.y + wv.z * a.z + wv.w * a.w;
            a = z4[1 * 104 + seg]; p1 += wv.x * a.x + wv.y * a.y + wv.z * a.z + wv.w * a.w;
            a = z4[2 * 104 + seg]; p2 += wv.x * a.x + wv.y * a.y + wv.z * a.z + wv.w * a.w;
            a = z4[3 * 104 + seg]; p3 += wv.x * a.x + wv.y * a.y + wv.z * a.z + wv.w * a.w;
            a = z4[4 * 104 + seg]; p4 += wv.x * a.x + wv.y * a.y + wv.z * a.z + wv.w * a.w;
            a = z4[5 * 104 + seg]; p5 += wv.x * a.x + wv.y * a.y + wv.z * a.z + wv.w * a.w;
            a = z4[6 * 104 + seg]; p6 += wv.x * a.x + wv.y * a.y + wv.z * a.z + wv.w * a.w;
            a = z4[7 * 104 + seg]; p7 += wv.x * a.x + wv.y * a.y + wv.z * a.z + wv.w * a.w;
        }
#pragma unroll
        for (int m = 16; m > 0; m >>= 1) {
            p0 += __shfl_xor_sync(0xffffffffu, p0, m);
            p1 += __shfl_xor_sync(0xffffffffu, p1, m);
            p2 += __shfl_xor_sync(0xffffffffu, p2, m);
            p3 += __shfl_xor_sync(0xffffffffu, p3, m);
            p4 += __shfl_xor_sync(0xffffffffu, p4, m);
            p5 += __shfl_xor_sync(0xffffffffu, p5, m);
            p6 += __shfl_xor_sync(0xffffffffu, p6, m);
            p7 += __shfl_xor_sync(0xffffffffu, p7, m);
        }
        if (lane == 0) {
            float bb = f1b[o];
            s_f[0 * 128 + o] = fmaxf(p0 + bb, 0.0f);
            s_f[1 * 128 + o] = fmaxf(p1 + bb, 0.0f);
            s_f[2 * 128 + o] = fmaxf(p2 + bb, 0.0f);
            s_f[3 * 128 + o] = fmaxf(p3 + bb, 0.0f);
            s_f[4 * 128 + o] = fmaxf(p4 + bb, 0.0f);
            s_f[5 * 128 + o] = fmaxf(p5 + bb, 0.0f);
            s_f[6 * 128 + o] = fmaxf(p6 + bb, 0.0f);
            s_f[7 * 128 + o] = fmaxf(p7 + bb, 0.0f);
        }
    }
    __syncthreads();

    float acc = f2w[lane]      * s_f[warp * 128 + lane]
              + f2w[lane + 32] * s_f[warp * 128 + lane + 32]
              + f2w[lane + 64] * s_f[warp * 128 + lane + 64]
              + f2w[lane + 96] * s_f[warp * 128 + lane + 96];
#pragma unroll
    for (int m = 16; m > 0; m >>= 1)
        acc += __shfl_xor_sync(0xffffffffu, acc, m);
    if (lane == 0) {
        float z = acc + f2b[0];
        out[g0 + warp] = 1.0f / (1.0f + expf(-z));
    }
}

// ---------------- launch -----------------------------------------------------
extern "C" void kernel_launch(void* const* d_in, const int* in_sizes, int n_in,
                              void* d_out, int out_size) {
    const float* x  = (const float*)d_in[0];
    const int*   ei = (const int*)d_in[1];   // int32 (JAX x64 disabled)
    const float* w[4] = {(const float*)d_in[3], (const float*)d_in[5],
                         (const float*)d_in[7], (const float*)d_in[9]};
    const float* b[4] = {(const float*)d_in[4], (const float*)d_in[6],
                         (const float*)d_in[8], (const float*)d_in[10]};
    const float* c1w = (const float*)d_in[11];
    const float* c1b = (const float*)d_in[12];
    const float* c2w = (const float*)d_in[13];
    const float* c2b = (const float*)d_in[14];
    const float* f1w = (const float*)d_in[15];
    const float* f1b = (const float*)d_in[16];
    const float* f2w = (const float*)d_in[17];
    const float* f2b = (const float*)d_in[18];
    float* out = (float*)d_out;

    const int eb = (NE + 255) / 256;
    const int nb = NN / 32;                 // 3125 blocks, 32 nodes each

    fill_kernel<<<eb, 256>>>(ei);

    gemm0_kernel<<<nb, 256>>>(x, w[0]);                 // -> hsA
    fused_kernel<<<nb, 256>>>(b[0], w[1], 0, 0);        // read A -> write B
    fused_kernel<<<nb, 256>>>(b[1], w[2], 1, 1);        // read B -> write A
    fused_kernel<<<nb, 256>>>(b[2], w[3], 2, 0);        // read A -> write B
    agg_final_kernel<<<nb, 256>>>(b[3], 1);             // read B, feat only

    head1_kernel<<<NG, 128>>>(c1w, c1b, c2w, c2b);
    head2_kernel<<<NG / 8, 256>>>(f1w, f1b, f2w, f2b, out);

    cleanup_kernel<<<(NN + 255) / 256, 256>>>();
}